// round 9
// baseline (speedup 1.0000x reference)
#include <cuda_runtime.h>
#include <cuda_bf16.h>
#include <cstdint>
#include <cstddef>

// ---------------------------------------------------------------------------
// Neural CDE classifier, ONE persistent clustered kernel + warp-level bf16
// mma.sync (3-pass hi/lo split ~ fp32 accuracy) for the big vf GEMM.
// grid = 128 CTAs = 16 clusters x 8, 512 thr/CTA, 1 CTA/SM.
// Cluster owns 32 batch elements; vf_W2 (2048x128) row-sliced 256 rows/CTA,
// stored as STATIC bf16 hi/lo [256][136] (row pad 272B -> conflict-free).
// Per RK4 substep:
//   L0 slice (scalar) -> allgather h0
//   L1 slice (scalar) -> allgather h1 as bf16 hi/lo into B operand [32][136]
//   16 warps x 96 mma.m16n8k16 (8 k-steps x 4 n-tiles x 3 hi/lo passes)
//   epilogue: tanh(+bias), dx contraction, warp butterfly over d, warp-pair
//   combine in smem, allgather k -> RK4 combine.  dt cancels; times unused.
// ---------------------------------------------------------------------------

typedef unsigned long long ull;

namespace {
constexpr int NSTEPS = 2047;
constexpr int KP2 = 272;   // padded row stride in BYTES (136 bf16)

// byte offsets in dynamic smem
constexpr int SB_AH = 0;        // 69632  W2 hi bf16 [256][136]
constexpr int SB_AL = 69632;    // 69632  W2 lo bf16 [256][136]
constexpr int SB_BH = 139264;   // 8704   h1 hi bf16 [32 b][136 k]
constexpr int SB_BL = 147968;   // 8704   h1 lo
constexpr int SB_W1 = 156672;   // 8192   fp32 W1 slice [16][128]
constexpr int SB_W0 = 164864;   // 4096   fp32 W0 slice [16][64]
constexpr int SB_B0 = 168960;   // 64
constexpr int SB_B1 = 169024;   // 64
constexpr int SB_Y  = 169088;   // 8192   y   [64][32] fp32
constexpr int SB_YIN= 177280;   // 8192   yin
constexpr int SB_KC = 185472;   // 8192   k   [64][32]
constexpr int SB_H0 = 193664;   // 16384  h0  [128][32] fp32
constexpr int SB_DX = 210048;   // 4224   dx  [32][33] fp32
constexpr int SB_KP = 214272;   // 2048   k partials [16 warp][32 b]
constexpr int SMEM_BYTES = 216320;
}

__device__ __forceinline__ uint32_t s2u(const void* p) {
    return (uint32_t)__cvta_generic_to_shared(p);
}
__device__ __forceinline__ uint32_t mapa_u(uint32_t laddr, int rank) {
    uint32_t r;
    asm("mapa.shared::cluster.u32 %0, %1, %2;" : "=r"(r) : "r"(laddr), "r"(rank));
    return r;
}
__device__ __forceinline__ void st_cluster32(uint32_t raddr, float v) {
    asm volatile("st.shared::cluster.f32 [%0], %1;" :: "r"(raddr), "f"(v) : "memory");
}
__device__ __forceinline__ void st_cluster16(uint32_t raddr, unsigned short v) {
    asm volatile("st.shared::cluster.b16 [%0], %1;" :: "r"(raddr), "h"(v) : "memory");
}
__device__ __forceinline__ void cluster_sync_() {
    asm volatile("barrier.cluster.arrive.aligned;" ::: "memory");
    asm volatile("barrier.cluster.wait.aligned;" ::: "memory");
}
__device__ __forceinline__ float tanh_f(float x) {
    float ax = fabsf(x);
    float e  = __expf(-2.0f * ax);
    float r  = __fdividef(1.0f - e, 1.0f + e);
    return copysignf(r, x);
}
__device__ __forceinline__ float gelu_f(float x) {
    float x3 = x * x * x;
    float t  = tanh_f(0.7978845608028654f * fmaf(0.044715f, x3, x));
    return 0.5f * x * (1.0f + t);
}
__device__ __forceinline__ void ldsm4(uint32_t (&r)[4], uint32_t addr) {
    asm volatile("ldmatrix.sync.aligned.m8n8.x4.shared.b16 {%0,%1,%2,%3}, [%4];"
                 : "=r"(r[0]), "=r"(r[1]), "=r"(r[2]), "=r"(r[3]) : "r"(addr));
}
__device__ __forceinline__ void mma16816(float (&c)[4], const uint32_t (&a)[4],
                                         uint32_t b0, uint32_t b1) {
    asm volatile(
        "mma.sync.aligned.m16n8k16.row.col.f32.bf16.bf16.f32 "
        "{%0,%1,%2,%3}, {%4,%5,%6,%7}, {%8,%9}, {%0,%1,%2,%3};"
        : "+f"(c[0]), "+f"(c[1]), "+f"(c[2]), "+f"(c[3])
        : "r"(a[0]), "r"(a[1]), "r"(a[2]), "r"(a[3]), "r"(b0), "r"(b1));
}

__global__ void __launch_bounds__(512, 1)
ncde_kernel(const float* __restrict__ xs,
            const float* __restrict__ eW0, const float* __restrict__ eb0,
            const float* __restrict__ eW1, const float* __restrict__ eb1,
            const float* __restrict__ eW2, const float* __restrict__ eb2,
            const float* __restrict__ vW0, const float* __restrict__ vb0,
            const float* __restrict__ vW1, const float* __restrict__ vb1,
            const float* __restrict__ vW2, const float* __restrict__ vb2,
            const float* __restrict__ dW,  const float* __restrict__ db,
            float* __restrict__ out)
{
    extern __shared__ char smc[];
    const int tid   = threadIdx.x;
    const int lane  = tid & 31;
    const int wid   = tid >> 5;          // 0..15
    const int rank  = blockIdx.x & 7;
    const int bbase = (blockIdx.x >> 3) * 32;

    float* sW1 = (float*)(smc + SB_W1);
    float* sW0 = (float*)(smc + SB_W0);
    float* sB0 = (float*)(smc + SB_B0);
    float* sB1 = (float*)(smc + SB_B1);
    float* sY  = (float*)(smc + SB_Y);
    float* sYI = (float*)(smc + SB_YIN);
    float* sKC = (float*)(smc + SB_KC);
    float* sH0 = (float*)(smc + SB_H0);
    float* sDX = (float*)(smc + SB_DX);
    float* sKP = (float*)(smc + SB_KP);

    const uint32_t smem_u = s2u(smc);

    // per-rank DSMEM address deltas (mapa is affine in the local address)
    uint32_t rdelta[8];
    #pragma unroll
    for (int r = 0; r < 8; ++r) rdelta[r] = mapa_u(smem_u, r) - smem_u;

    // xs mapping: thread owns (b = tid>>4, d = 2*(tid&15), +1)
    const int xb  = tid >> 4;
    const int xd2 = tid & 15;
    const float* xsrow = xs + (size_t)(bbase + xb) * 2048 * 32 + xd2 * 2;

    float xc0, xc1;
    {
        float2 v = *reinterpret_cast<const float2*>(xsrow);
        xc0 = v.x; xc1 = v.y;
        sKC[(2 * xd2) * 32 + xb]     = v.x;   // stage xs0 d-major for encoder
        sKC[(2 * xd2 + 1) * 32 + xb] = v.y;
    }

    // ---- encoder weights transposed into A scratch (floats) ----
    float* sE0 = (float*)(smc + SB_AH);          // [32][128]
    float* sE1 = sE0 + 4096;                     // [128][128]
    float* sE2 = sE0 + 20480;                    // [128][64]
    float* sEH = sE0 + 28672;                    // [128][32]
    for (int i = tid; i < 4096;  i += 512) { int r = i & 127, kk = i >> 7; sE0[i] = eW0[r * 32  + kk]; }
    for (int i = tid; i < 16384; i += 512) { int r = i & 127, kk = i >> 7; sE1[i] = eW1[r * 128 + kk]; }
    for (int i = tid; i < 8192;  i += 512) { int r = i & 63,  kk = i >> 6; sE2[i] = eW2[r * 128 + kk]; }
    __syncthreads();

    // ---- encoder (replicated per CTA): sKC(xs0) -> sH0 -> sEH -> sY ----
    {
        int b = lane, rbase = wid * 8;
        float acc[8];
        #pragma unroll
        for (int j = 0; j < 8; ++j) acc[j] = eb0[rbase + j];
        for (int kk = 0; kk < 32; ++kk) {
            float x = sKC[kk * 32 + b];
            #pragma unroll
            for (int j = 0; j < 8; ++j) acc[j] = fmaf(sE0[kk * 128 + rbase + j], x, acc[j]);
        }
        #pragma unroll
        for (int j = 0; j < 8; ++j) sH0[(rbase + j) * 32 + b] = fmaxf(acc[j], 0.0f);
    }
    __syncthreads();
    {
        int b = lane, rbase = wid * 8;
        float acc[8];
        #pragma unroll
        for (int j = 0; j < 8; ++j) acc[j] = eb1[rbase + j];
        for (int kk = 0; kk < 128; ++kk) {
            float x = sH0[kk * 32 + b];
            #pragma unroll
            for (int j = 0; j < 8; ++j) acc[j] = fmaf(sE1[kk * 128 + rbase + j], x, acc[j]);
        }
        #pragma unroll
        for (int j = 0; j < 8; ++j) sEH[(rbase + j) * 32 + b] = fmaxf(acc[j], 0.0f);
    }
    __syncthreads();
    {
        int b = lane, rbase = wid * 4;
        float acc[4];
        #pragma unroll
        for (int j = 0; j < 4; ++j) acc[j] = eb2[rbase + j];
        for (int kk = 0; kk < 128; ++kk) {
            float x = sEH[kk * 32 + b];
            #pragma unroll
            for (int j = 0; j < 4; ++j) acc[j] = fmaf(sE2[kk * 64 + rbase + j], x, acc[j]);
        }
        #pragma unroll
        for (int j = 0; j < 4; ++j) sY[(rbase + j) * 32 + b] = acc[j];
    }
    __syncthreads();

    // ---- build static bf16 hi/lo A operand (overwrites encoder scratch) ----
    for (int i = tid; i < 32768; i += 512) {
        int m = i >> 7, k = i & 127;
        float w = vW2[(size_t)(rank * 256 + m) * 128 + k];
        __nv_bfloat16 hb = __float2bfloat16(w);
        float hf = __bfloat162float(hb);
        __nv_bfloat16 lb = __float2bfloat16(w - hf);
        *(__nv_bfloat16*)(smc + SB_AH + m * KP2 + k * 2) = hb;
        *(__nv_bfloat16*)(smc + SB_AL + m * KP2 + k * 2) = lb;
    }
    for (int i = tid; i < 2048; i += 512) {
        int kk = i & 127, r = i >> 7;
        sW1[i] = vW1[(rank * 16 + r) * 128 + kk];
    }
    for (int i = tid; i < 1024; i += 512) {
        int kk = i & 63, r = i >> 6;
        sW0[i] = vW0[(rank * 16 + r) * 64 + kk];
    }
    if (tid < 16)      sB0[tid]      = vb0[rank * 16 + tid];
    else if (tid < 32) sB1[tid - 16] = vb1[rank * 16 + tid - 16];
    cluster_sync_();

    // ---- per-thread invariants ----
    const int g  = lane >> 2;           // mma group id
    const int tg = lane & 3;            // thread in group
    const float b0s = sB0[wid];
    const float b1s = sB1[wid];
    const uint32_t aH0 = s2u(&sH0[(rank * 16 + wid) * 32 + lane]);
    const int kg = rank * 16 + wid;     // global k row produced by this thread in L1
    const uint32_t aBHw = smem_u + SB_BH + (uint32_t)lane * KP2 + kg * 2;
    const uint32_t aBLw = smem_u + SB_BL + (uint32_t)lane * KP2 + kg * 2;

    // A ldmatrix addresses (per k-step add 32B): rows wid*16 + (lane&15), chunk (lane>>4)*16
    const uint32_t aAH = smem_u + SB_AH + (uint32_t)(wid * 16 + (lane & 15)) * KP2 + (lane >> 4) * 16;
    const uint32_t aAL = aAH + (SB_AL - SB_AH);

    // B manual-load bases: row n = g (within n-tile), col bytes kk*32 + tg*4
    const uint32_t aBH = smem_u + SB_BH + (uint32_t)g * KP2 + tg * 4;
    const uint32_t aBL = aBH + (SB_BL - SB_BH);

    // epilogue invariants
    const float b2a = vb2[rank * 256 + wid * 16 + g];
    const float b2b = vb2[rank * 256 + wid * 16 + g + 8];
    const int d0 = (wid & 1) * 16 + g;
    uint32_t aKC = 0;
    if (wid < 8) aKC = s2u(&sKC[(rank * 8 + wid) * 32 + lane]);

    // ---- main RK4 scan ----
    for (int t = 0; t < NSTEPS; ++t) {
        float2 xn = *reinterpret_cast<const float2*>(xsrow + (size_t)(t + 1) * 32);
        float ks0, ks1, ks2, ks3;

        #pragma unroll
        for (int s = 0; s < 4; ++s) {
            const float* yin = (s == 0) ? sY : sYI;

            // ---- L0: h0[wid][lane] = gelu(W0row . yin + b0), push to 8 ranks
            {
                float a = b0s;
                const float* wrow = sW0 + wid * 64;
                #pragma unroll
                for (int k4 = 0; k4 < 16; ++k4) {
                    float4 w4 = *reinterpret_cast<const float4*>(wrow + k4 * 4);
                    a = fmaf(w4.x, yin[(k4 * 4 + 0) * 32 + lane], a);
                    a = fmaf(w4.y, yin[(k4 * 4 + 1) * 32 + lane], a);
                    a = fmaf(w4.z, yin[(k4 * 4 + 2) * 32 + lane], a);
                    a = fmaf(w4.w, yin[(k4 * 4 + 3) * 32 + lane], a);
                }
                a = gelu_f(a);
                #pragma unroll
                for (int r = 0; r < 8; ++r) st_cluster32(aH0 + rdelta[r], a);
            }
            if (s == 0) {
                float dd0 = xn.x - xc0, dd1 = xn.y - xc1;
                xc0 = xn.x; xc1 = xn.y;
                sDX[(2 * xd2) * 33 + xb]     = dd0;
                sDX[(2 * xd2 + 1) * 33 + xb] = dd1;
            }
            cluster_sync_();  // B1: h0 + dx ready everywhere

            // ---- L1: h1[kg][lane] = gelu(W1row . h0 + b1) -> bf16 hi/lo B op
            {
                float a = b1s;
                const float* wrow = sW1 + wid * 128;
                #pragma unroll 8
                for (int k4 = 0; k4 < 32; ++k4) {
                    float4 w4 = *reinterpret_cast<const float4*>(wrow + k4 * 4);
                    a = fmaf(w4.x, sH0[(k4 * 4 + 0) * 32 + lane], a);
                    a = fmaf(w4.y, sH0[(k4 * 4 + 1) * 32 + lane], a);
                    a = fmaf(w4.z, sH0[(k4 * 4 + 2) * 32 + lane], a);
                    a = fmaf(w4.w, sH0[(k4 * 4 + 3) * 32 + lane], a);
                }
                a = gelu_f(a);
                __nv_bfloat16 hb = __float2bfloat16(a);
                float hf = __bfloat162float(hb);
                __nv_bfloat16 lb = __float2bfloat16(a - hf);
                unsigned short hu = reinterpret_cast<unsigned short&>(hb);
                unsigned short lu = reinterpret_cast<unsigned short&>(lb);
                #pragma unroll
                for (int r = 0; r < 8; ++r) {
                    st_cluster16(aBHw + rdelta[r], hu);
                    st_cluster16(aBLw + rdelta[r], lu);
                }
            }
            cluster_sync_();  // B2: B operand ready everywhere

            // ---- W2 GEMM via mma.sync, 3-pass bf16 hi/lo ----
            float acc[4][4];
            #pragma unroll
            for (int nt = 0; nt < 4; ++nt)
                #pragma unroll
                for (int i = 0; i < 4; ++i) acc[nt][i] = 0.0f;

            #pragma unroll
            for (int kk = 0; kk < 8; ++kk) {
                uint32_t ah[4], al[4];
                ldsm4(ah, aAH + kk * 32);
                ldsm4(al, aAL + kk * 32);
                #pragma unroll
                for (int nt = 0; nt < 4; ++nt) {
                    uint32_t rb = (uint32_t)(nt * 8) * KP2 + kk * 32;
                    uint32_t bh0 = *(const uint32_t*)(smc + (aBH - smem_u) + rb);
                    uint32_t bh1 = *(const uint32_t*)(smc + (aBH - smem_u) + rb + 16);
                    uint32_t bl0 = *(const uint32_t*)(smc + (aBL - smem_u) + rb);
                    uint32_t bl1 = *(const uint32_t*)(smc + (aBL - smem_u) + rb + 16);
                    mma16816(acc[nt], ah, bh0, bh1);   // hi * hi
                    mma16816(acc[nt], ah, bl0, bl1);   // hi * lo
                    mma16816(acc[nt], al, bh0, bh1);   // lo * hi
                }
            }

            // ---- epilogue: tanh(+bias) * dx, reduce over d ----
            {
                float p[8];
                #pragma unroll
                for (int nt = 0; nt < 4; ++nt) {
                    int b0i = nt * 8 + tg * 2;
                    float u00 = tanh_f(acc[nt][0] + b2a);
                    float u01 = tanh_f(acc[nt][1] + b2a);
                    float u10 = tanh_f(acc[nt][2] + b2b);
                    float u11 = tanh_f(acc[nt][3] + b2b);
                    p[nt * 2 + 0] = fmaf(u00, sDX[d0 * 33 + b0i],
                                         u10 * sDX[(d0 + 8) * 33 + b0i]);
                    p[nt * 2 + 1] = fmaf(u01, sDX[d0 * 33 + b0i + 1],
                                         u11 * sDX[(d0 + 8) * 33 + b0i + 1]);
                }
                #pragma unroll
                for (int m = 4; m <= 16; m <<= 1)
                    #pragma unroll
                    for (int i = 0; i < 8; ++i)
                        p[i] += __shfl_xor_sync(0xffffffffu, p[i], m);
                if (lane < 4) {
                    #pragma unroll
                    for (int nt = 0; nt < 4; ++nt) {
                        float2 v = make_float2(p[nt * 2], p[nt * 2 + 1]);
                        *reinterpret_cast<float2*>(&sKP[wid * 32 + nt * 8 + tg * 2]) = v;
                    }
                }
            }
            __syncthreads();
            if (wid < 8) {
                float v = sKP[(2 * wid) * 32 + lane] + sKP[(2 * wid + 1) * 32 + lane];
                #pragma unroll
                for (int r = 0; r < 8; ++r) st_cluster32(aKC + rdelta[r], v);
            }
            cluster_sync_();  // B3: k ready everywhere

            // ---- RK4 combine (thread owns y elements [tid*4, tid*4+4)) ----
            {
                const int f = tid * 4;
                float4 k4 = *reinterpret_cast<float4*>(&sKC[f]);
                if (s == 0) {
                    ks0 = k4.x; ks1 = k4.y; ks2 = k4.z; ks3 = k4.w;
                } else {
                    const float w_s = (s == 3) ? 1.0f : 2.0f;
                    ks0 = fmaf(w_s, k4.x, ks0); ks1 = fmaf(w_s, k4.y, ks1);
                    ks2 = fmaf(w_s, k4.z, ks2); ks3 = fmaf(w_s, k4.w, ks3);
                }
                float4 y4 = *reinterpret_cast<float4*>(&sY[f]);
                if (s < 3) {
                    const float c = (s == 2) ? 1.0f : 0.5f;
                    float4 a;
                    a.x = fmaf(c, k4.x, y4.x); a.y = fmaf(c, k4.y, y4.y);
                    a.z = fmaf(c, k4.z, y4.z); a.w = fmaf(c, k4.w, y4.w);
                    *reinterpret_cast<float4*>(&sYI[f]) = a;
                } else {
                    const float sx = 1.0f / 6.0f;
                    y4.x = fmaf(sx, ks0, y4.x); y4.y = fmaf(sx, ks1, y4.y);
                    y4.z = fmaf(sx, ks2, y4.z); y4.w = fmaf(sx, ks3, y4.w);
                    *reinterpret_cast<float4*>(&sY[f]) = y4;
                }
            }
            __syncthreads();
        }
    }

    // ---- decoder + sigmoid (rank 0 CTA) ----
    if (rank == 0 && tid < 32) {
        float acc = db[0];
        #pragma unroll 8
        for (int r = 0; r < 64; ++r) acc = fmaf(dW[r], sY[r * 32 + tid], acc);
        out[bbase + tid] = __fdividef(1.0f, 1.0f + __expf(-acc));
    }
}

extern "C" void kernel_launch(void* const* d_in, const int* in_sizes, int n_in,
                              void* d_out, int out_size) {
    (void)in_sizes; (void)n_in; (void)out_size;
    const float* xs  = (const float*)d_in[1];
    const float* eW0 = (const float*)d_in[2];
    const float* eb0 = (const float*)d_in[3];
    const float* eW1 = (const float*)d_in[4];
    const float* eb1 = (const float*)d_in[5];
    const float* eW2 = (const float*)d_in[6];
    const float* eb2 = (const float*)d_in[7];
    const float* vW0 = (const float*)d_in[8];
    const float* vb0 = (const float*)d_in[9];
    const float* vW1 = (const float*)d_in[10];
    const float* vb1 = (const float*)d_in[11];
    const float* vW2 = (const float*)d_in[12];
    const float* vb2 = (const float*)d_in[13];
    const float* dW  = (const float*)d_in[14];
    const float* db  = (const float*)d_in[15];
    float* out = (float*)d_out;

    cudaFuncSetAttribute(ncde_kernel, cudaFuncAttributeMaxDynamicSharedMemorySize, SMEM_BYTES);

    cudaLaunchConfig_t cfg = {};
    cfg.gridDim  = dim3(128, 1, 1);
    cfg.blockDim = dim3(512, 1, 1);
    cfg.dynamicSmemBytes = SMEM_BYTES;
    cfg.stream = 0;
    cudaLaunchAttribute attrs[1];
    attrs[0].id = cudaLaunchAttributeClusterDimension;
    attrs[0].val.clusterDim.x = 8;
    attrs[0].val.clusterDim.y = 1;
    attrs[0].val.clusterDim.z = 1;
    cfg.attrs = attrs;
    cfg.numAttrs = 1;

    cudaLaunchKernelEx(&cfg, ncde_kernel,
                       xs, eW0, eb0, eW1, eb1, eW2, eb2,
                       vW0, vb0, vW1, vb1, vW2, vb2, dW, db, out);
}

// round 10
// speedup vs baseline: 1.7205x; 1.7205x over previous
#include <cuda_runtime.h>
#include <cuda_bf16.h>
#include <cstdint>
#include <cstddef>

// ---------------------------------------------------------------------------
// Neural CDE classifier, ONE persistent clustered kernel + warp-level bf16
// mma.sync (3-pass hi/lo split ~ fp32 accuracy) for the big vf GEMM.
// R10: ALL DSMEM pushes are 128-bit (quad-gather + st.shared::cluster.v4);
// h1 staged as packed (hi|lo) u32 [k][36] so one 32-bit push carries both
// halves; W2 B-fragments extracted with PRMT (no extra LDS).
// grid = 128 CTAs = 16 clusters x 8, 512 thr/CTA, 1 CTA/SM.
// ---------------------------------------------------------------------------

typedef unsigned long long ull;

namespace {
constexpr int NSTEPS = 2047;
constexpr int KP2 = 272;   // A-operand padded row stride in BYTES (136 bf16)

// byte offsets in dynamic smem
constexpr int SB_AH = 0;        // 69632  W2 hi bf16 [256][136]
constexpr int SB_AL = 69632;    // 69632  W2 lo bf16 [256][136]
constexpr int SB_PK = 139264;   // 18432  h1 packed u32 (hi|lo) [128 k][36]
constexpr int SB_W1 = 157696;   // 8192   fp32 W1 slice [16][128]
constexpr int SB_W0 = 165888;   // 4096   fp32 W0 slice [16][64]
constexpr int SB_B0 = 169984;   // 64
constexpr int SB_B1 = 170048;   // 64
constexpr int SB_Y  = 170112;   // 8192   y   [64][32] fp32
constexpr int SB_YIN= 178304;   // 8192   yin
constexpr int SB_KC = 186496;   // 8192   k   [64][32]
constexpr int SB_H0 = 194688;   // 16384  h0  [128][32] fp32
constexpr int SB_DX = 211072;   // 4224   dx  [32][33] fp32
constexpr int SB_KP = 215296;   // 2048   k partials [16 warp][32 b]
constexpr int SMEM_BYTES = 217344;
}

__device__ __forceinline__ uint32_t s2u(const void* p) {
    return (uint32_t)__cvta_generic_to_shared(p);
}
__device__ __forceinline__ uint32_t mapa_u(uint32_t laddr, int rank) {
    uint32_t r;
    asm("mapa.shared::cluster.u32 %0, %1, %2;" : "=r"(r) : "r"(laddr), "r"(rank));
    return r;
}
__device__ __forceinline__ void st_cl128f(uint32_t raddr, float a, float b, float c, float d) {
    asm volatile("st.shared::cluster.v4.f32 [%0], {%1,%2,%3,%4};"
                 :: "r"(raddr), "f"(a), "f"(b), "f"(c), "f"(d) : "memory");
}
__device__ __forceinline__ void st_cl128u(uint32_t raddr, uint32_t a, uint32_t b,
                                          uint32_t c, uint32_t d) {
    asm volatile("st.shared::cluster.v4.b32 [%0], {%1,%2,%3,%4};"
                 :: "r"(raddr), "r"(a), "r"(b), "r"(c), "r"(d) : "memory");
}
__device__ __forceinline__ void cluster_sync_() {
    asm volatile("barrier.cluster.arrive.aligned;" ::: "memory");
    asm volatile("barrier.cluster.wait.aligned;" ::: "memory");
}
__device__ __forceinline__ uint32_t prmt(uint32_t a, uint32_t b, uint32_t sel) {
    uint32_t d;
    asm("prmt.b32 %0, %1, %2, %3;" : "=r"(d) : "r"(a), "r"(b), "r"(sel));
    return d;
}
__device__ __forceinline__ float tanh_f(float x) {
    float ax = fabsf(x);
    float e  = __expf(-2.0f * ax);
    float r  = __fdividef(1.0f - e, 1.0f + e);
    return copysignf(r, x);
}
__device__ __forceinline__ float gelu_f(float x) {
    float x3 = x * x * x;
    float t  = tanh_f(0.7978845608028654f * fmaf(0.044715f, x3, x));
    return 0.5f * x * (1.0f + t);
}
__device__ __forceinline__ void ldsm4(uint32_t (&r)[4], uint32_t addr) {
    asm volatile("ldmatrix.sync.aligned.m8n8.x4.shared.b16 {%0,%1,%2,%3}, [%4];"
                 : "=r"(r[0]), "=r"(r[1]), "=r"(r[2]), "=r"(r[3]) : "r"(addr));
}
__device__ __forceinline__ void mma16816(float (&c)[4], const uint32_t (&a)[4],
                                         uint32_t b0, uint32_t b1) {
    asm volatile(
        "mma.sync.aligned.m16n8k16.row.col.f32.bf16.bf16.f32 "
        "{%0,%1,%2,%3}, {%4,%5,%6,%7}, {%8,%9}, {%0,%1,%2,%3};"
        : "+f"(c[0]), "+f"(c[1]), "+f"(c[2]), "+f"(c[3])
        : "r"(a[0]), "r"(a[1]), "r"(a[2]), "r"(a[3]), "r"(b0), "r"(b1));
}

__global__ void __launch_bounds__(512, 1)
ncde_kernel(const float* __restrict__ xs,
            const float* __restrict__ eW0, const float* __restrict__ eb0,
            const float* __restrict__ eW1, const float* __restrict__ eb1,
            const float* __restrict__ eW2, const float* __restrict__ eb2,
            const float* __restrict__ vW0, const float* __restrict__ vb0,
            const float* __restrict__ vW1, const float* __restrict__ vb1,
            const float* __restrict__ vW2, const float* __restrict__ vb2,
            const float* __restrict__ dW,  const float* __restrict__ db,
            float* __restrict__ out)
{
    extern __shared__ char smc[];
    const int tid   = threadIdx.x;
    const int lane  = tid & 31;
    const int wid   = tid >> 5;          // 0..15
    const int rank  = blockIdx.x & 7;
    const int bbase = (blockIdx.x >> 3) * 32;

    float* sW1 = (float*)(smc + SB_W1);
    float* sW0 = (float*)(smc + SB_W0);
    float* sB0 = (float*)(smc + SB_B0);
    float* sB1 = (float*)(smc + SB_B1);
    float* sY  = (float*)(smc + SB_Y);
    float* sYI = (float*)(smc + SB_YIN);
    float* sKC = (float*)(smc + SB_KC);
    float* sH0 = (float*)(smc + SB_H0);
    float* sDX = (float*)(smc + SB_DX);
    float* sKP = (float*)(smc + SB_KP);
    const uint32_t* sPK = (const uint32_t*)(smc + SB_PK);

    const uint32_t smem_u = s2u(smc);

    // per-rank DSMEM address deltas (mapa is affine in the local address)
    uint32_t rdelta[8];
    #pragma unroll
    for (int r = 0; r < 8; ++r) rdelta[r] = mapa_u(smem_u, r) - smem_u;

    // xs mapping: thread owns (b = tid>>4, d = 2*(tid&15), +1)
    const int xb  = tid >> 4;
    const int xd2 = tid & 15;
    const float* xsrow = xs + (size_t)(bbase + xb) * 2048 * 32 + xd2 * 2;

    float xc0, xc1;
    {
        float2 v = *reinterpret_cast<const float2*>(xsrow);
        xc0 = v.x; xc1 = v.y;
        sKC[(2 * xd2) * 32 + xb]     = v.x;   // stage xs0 d-major for encoder
        sKC[(2 * xd2 + 1) * 32 + xb] = v.y;
    }

    // ---- encoder weights transposed into A scratch (floats) ----
    float* sE0 = (float*)(smc + SB_AH);          // [32][128]
    float* sE1 = sE0 + 4096;                     // [128][128]
    float* sE2 = sE0 + 20480;                    // [128][64]
    float* sEH = sE0 + 28672;                    // [128][32]
    for (int i = tid; i < 4096;  i += 512) { int r = i & 127, kk = i >> 7; sE0[i] = eW0[r * 32  + kk]; }
    for (int i = tid; i < 16384; i += 512) { int r = i & 127, kk = i >> 7; sE1[i] = eW1[r * 128 + kk]; }
    for (int i = tid; i < 8192;  i += 512) { int r = i & 63,  kk = i >> 6; sE2[i] = eW2[r * 128 + kk]; }
    __syncthreads();

    // ---- encoder (replicated per CTA): sKC(xs0) -> sH0 -> sEH -> sY ----
    {
        int b = lane, rbase = wid * 8;
        float acc[8];
        #pragma unroll
        for (int j = 0; j < 8; ++j) acc[j] = eb0[rbase + j];
        for (int kk = 0; kk < 32; ++kk) {
            float x = sKC[kk * 32 + b];
            #pragma unroll
            for (int j = 0; j < 8; ++j) acc[j] = fmaf(sE0[kk * 128 + rbase + j], x, acc[j]);
        }
        #pragma unroll
        for (int j = 0; j < 8; ++j) sH0[(rbase + j) * 32 + b] = fmaxf(acc[j], 0.0f);
    }
    __syncthreads();
    {
        int b = lane, rbase = wid * 8;
        float acc[8];
        #pragma unroll
        for (int j = 0; j < 8; ++j) acc[j] = eb1[rbase + j];
        for (int kk = 0; kk < 128; ++kk) {
            float x = sH0[kk * 32 + b];
            #pragma unroll
            for (int j = 0; j < 8; ++j) acc[j] = fmaf(sE1[kk * 128 + rbase + j], x, acc[j]);
        }
        #pragma unroll
        for (int j = 0; j < 8; ++j) sEH[(rbase + j) * 32 + b] = fmaxf(acc[j], 0.0f);
    }
    __syncthreads();
    {
        int b = lane, rbase = wid * 4;
        float acc[4];
        #pragma unroll
        for (int j = 0; j < 4; ++j) acc[j] = eb2[rbase + j];
        for (int kk = 0; kk < 128; ++kk) {
            float x = sEH[kk * 32 + b];
            #pragma unroll
            for (int j = 0; j < 4; ++j) acc[j] = fmaf(sE2[kk * 64 + rbase + j], x, acc[j]);
        }
        #pragma unroll
        for (int j = 0; j < 4; ++j) sY[(rbase + j) * 32 + b] = acc[j];
    }
    __syncthreads();

    // ---- build static bf16 hi/lo A operand (overwrites encoder scratch) ----
    for (int i = tid; i < 32768; i += 512) {
        int m = i >> 7, k = i & 127;
        float w = vW2[(size_t)(rank * 256 + m) * 128 + k];
        __nv_bfloat16 hb = __float2bfloat16(w);
        float hf = __bfloat162float(hb);
        __nv_bfloat16 lb = __float2bfloat16(w - hf);
        *(__nv_bfloat16*)(smc + SB_AH + m * KP2 + k * 2) = hb;
        *(__nv_bfloat16*)(smc + SB_AL + m * KP2 + k * 2) = lb;
    }
    for (int i = tid; i < 2048; i += 512) {
        int kk = i & 127, r = i >> 7;
        sW1[i] = vW1[(rank * 16 + r) * 128 + kk];
    }
    for (int i = tid; i < 1024; i += 512) {
        int kk = i & 63, r = i >> 6;
        sW0[i] = vW0[(rank * 16 + r) * 64 + kk];
    }
    if (tid < 16)      sB0[tid]      = vb0[rank * 16 + tid];
    else if (tid < 32) sB1[tid - 16] = vb1[rank * 16 + tid - 16];
    cluster_sync_();

    // ---- per-thread invariants ----
    const int g  = lane >> 2;           // mma group id
    const int tg = lane & 3;            // thread in group
    const float b0s = sB0[wid];
    const float b1s = sB1[wid];
    const uint32_t aH0 = s2u(&sH0[(rank * 16 + wid) * 32 + lane]);   // lane%4==0 stores v4
    const int kg = rank * 16 + wid;     // global k row produced by this thread in L1
    const uint32_t aPK = smem_u + SB_PK + (uint32_t)(kg * 36 + lane) * 4;

    // A ldmatrix addresses (per k-step add 32B)
    const uint32_t aAH = smem_u + SB_AH + (uint32_t)(wid * 16 + (lane & 15)) * KP2 + (lane >> 4) * 16;
    const uint32_t aAL = aAH + (SB_AL - SB_AH);

    // B fragment source (packed): per-thread base index into sPK
    const uint32_t* pkT = sPK + tg * 2 * 36 + g;   // + nt*8 + kk*16*36 + {0,36,288,324}

    // epilogue invariants
    const float b2a = vb2[rank * 256 + wid * 16 + g];
    const float b2b = vb2[rank * 256 + wid * 16 + g + 8];
    const int d0 = (wid & 1) * 16 + g;
    uint32_t aKC = 0;
    if (wid < 8) aKC = s2u(&sKC[(rank * 8 + wid) * 32 + lane]);

    // ---- main RK4 scan ----
    for (int t = 0; t < NSTEPS; ++t) {
        float2 xn = *reinterpret_cast<const float2*>(xsrow + (size_t)(t + 1) * 32);
        float ks0, ks1, ks2, ks3;

        #pragma unroll
        for (int s = 0; s < 4; ++s) {
            const float* yin = (s == 0) ? sY : sYI;

            // ---- L0: h0[wid][lane] = gelu(W0row . yin + b0), wide push ----
            {
                float a = b0s;
                const float* wrow = sW0 + wid * 64;
                #pragma unroll
                for (int k4 = 0; k4 < 16; ++k4) {
                    float4 w4 = *reinterpret_cast<const float4*>(wrow + k4 * 4);
                    a = fmaf(w4.x, yin[(k4 * 4 + 0) * 32 + lane], a);
                    a = fmaf(w4.y, yin[(k4 * 4 + 1) * 32 + lane], a);
                    a = fmaf(w4.z, yin[(k4 * 4 + 2) * 32 + lane], a);
                    a = fmaf(w4.w, yin[(k4 * 4 + 3) * 32 + lane], a);
                }
                a = gelu_f(a);
                float a1 = __shfl_down_sync(0xffffffffu, a, 1);
                float a2 = __shfl_down_sync(0xffffffffu, a, 2);
                float a3 = __shfl_down_sync(0xffffffffu, a, 3);
                if ((lane & 3) == 0) {
                    #pragma unroll
                    for (int r = 0; r < 8; ++r) st_cl128f(aH0 + rdelta[r], a, a1, a2, a3);
                }
            }
            if (s == 0) {
                float dd0 = xn.x - xc0, dd1 = xn.y - xc1;
                xc0 = xn.x; xc1 = xn.y;
                sDX[(2 * xd2) * 33 + xb]     = dd0;
                sDX[(2 * xd2 + 1) * 33 + xb] = dd1;
            }
            cluster_sync_();  // B1: h0 + dx ready everywhere

            // ---- L1: h1[kg][lane] -> packed (hi|lo) u32, wide push ----
            {
                float a = b1s;
                const float* wrow = sW1 + wid * 128;
                #pragma unroll 8
                for (int k4 = 0; k4 < 32; ++k4) {
                    float4 w4 = *reinterpret_cast<const float4*>(wrow + k4 * 4);
                    a = fmaf(w4.x, sH0[(k4 * 4 + 0) * 32 + lane], a);
                    a = fmaf(w4.y, sH0[(k4 * 4 + 1) * 32 + lane], a);
                    a = fmaf(w4.z, sH0[(k4 * 4 + 2) * 32 + lane], a);
                    a = fmaf(w4.w, sH0[(k4 * 4 + 3) * 32 + lane], a);
                }
                a = gelu_f(a);
                __nv_bfloat16 hb = __float2bfloat16(a);
                float hf = __bfloat162float(hb);
                __nv_bfloat16 lb = __float2bfloat16(a - hf);
                uint32_t w = (uint32_t)reinterpret_cast<unsigned short&>(hb) |
                             ((uint32_t)reinterpret_cast<unsigned short&>(lb) << 16);
                uint32_t w1 = __shfl_down_sync(0xffffffffu, w, 1);
                uint32_t w2 = __shfl_down_sync(0xffffffffu, w, 2);
                uint32_t w3 = __shfl_down_sync(0xffffffffu, w, 3);
                if ((lane & 3) == 0) {
                    #pragma unroll
                    for (int r = 0; r < 8; ++r) st_cl128u(aPK + rdelta[r], w, w1, w2, w3);
                }
            }
            cluster_sync_();  // B2: packed B operand ready everywhere

            // ---- W2 GEMM via mma.sync, 3-pass bf16 hi/lo ----
            float acc[4][4];
            #pragma unroll
            for (int nt = 0; nt < 4; ++nt)
                #pragma unroll
                for (int i = 0; i < 4; ++i) acc[nt][i] = 0.0f;

            #pragma unroll
            for (int kk = 0; kk < 8; ++kk) {
                uint32_t ah[4], al[4];
                ldsm4(ah, aAH + kk * 32);
                ldsm4(al, aAL + kk * 32);
                const uint32_t* pkk = pkT + kk * 16 * 36;
                #pragma unroll
                for (int nt = 0; nt < 4; ++nt) {
                    uint32_t w0 = pkk[nt * 8];
                    uint32_t w1 = pkk[nt * 8 + 36];
                    uint32_t w8 = pkk[nt * 8 + 8 * 36];
                    uint32_t w9 = pkk[nt * 8 + 9 * 36];
                    uint32_t bh0 = prmt(w0, w1, 0x5410u);
                    uint32_t bl0 = prmt(w0, w1, 0x7632u);
                    uint32_t bh1 = prmt(w8, w9, 0x5410u);
                    uint32_t bl1 = prmt(w8, w9, 0x7632u);
                    mma16816(acc[nt], ah, bh0, bh1);   // hi * hi
                    mma16816(acc[nt], ah, bl0, bl1);   // hi * lo
                    mma16816(acc[nt], al, bh0, bh1);   // lo * hi
                }
            }

            // ---- epilogue: tanh(+bias) * dx, reduce over d ----
            {
                float p[8];
                #pragma unroll
                for (int nt = 0; nt < 4; ++nt) {
                    int b0i = nt * 8 + tg * 2;
                    float u00 = tanh_f(acc[nt][0] + b2a);
                    float u01 = tanh_f(acc[nt][1] + b2a);
                    float u10 = tanh_f(acc[nt][2] + b2b);
                    float u11 = tanh_f(acc[nt][3] + b2b);
                    p[nt * 2 + 0] = fmaf(u00, sDX[d0 * 33 + b0i],
                                         u10 * sDX[(d0 + 8) * 33 + b0i]);
                    p[nt * 2 + 1] = fmaf(u01, sDX[d0 * 33 + b0i + 1],
                                         u11 * sDX[(d0 + 8) * 33 + b0i + 1]);
                }
                #pragma unroll
                for (int m = 4; m <= 16; m <<= 1)
                    #pragma unroll
                    for (int i = 0; i < 8; ++i)
                        p[i] += __shfl_xor_sync(0xffffffffu, p[i], m);
                if (lane < 4) {
                    #pragma unroll
                    for (int nt = 0; nt < 4; ++nt) {
                        float2 v = make_float2(p[nt * 2], p[nt * 2 + 1]);
                        *reinterpret_cast<float2*>(&sKP[wid * 32 + nt * 8 + tg * 2]) = v;
                    }
                }
            }
            __syncthreads();
            if (wid < 8) {
                float v = sKP[(2 * wid) * 32 + lane] + sKP[(2 * wid + 1) * 32 + lane];
                float v1 = __shfl_down_sync(0xffffffffu, v, 1);
                float v2 = __shfl_down_sync(0xffffffffu, v, 2);
                float v3 = __shfl_down_sync(0xffffffffu, v, 3);
                if ((lane & 3) == 0) {
                    #pragma unroll
                    for (int r = 0; r < 8; ++r) st_cl128f(aKC + rdelta[r], v, v1, v2, v3);
                }
            }
            cluster_sync_();  // B3: k ready everywhere

            // ---- RK4 combine (thread owns y elements [tid*4, tid*4+4)) ----
            {
                const int f = tid * 4;
                float4 k4 = *reinterpret_cast<float4*>(&sKC[f]);
                if (s == 0) {
                    ks0 = k4.x; ks1 = k4.y; ks2 = k4.z; ks3 = k4.w;
                } else {
                    const float w_s = (s == 3) ? 1.0f : 2.0f;
                    ks0 = fmaf(w_s, k4.x, ks0); ks1 = fmaf(w_s, k4.y, ks1);
                    ks2 = fmaf(w_s, k4.z, ks2); ks3 = fmaf(w_s, k4.w, ks3);
                }
                float4 y4 = *reinterpret_cast<float4*>(&sY[f]);
                if (s < 3) {
                    const float c = (s == 2) ? 1.0f : 0.5f;
                    float4 a;
                    a.x = fmaf(c, k4.x, y4.x); a.y = fmaf(c, k4.y, y4.y);
                    a.z = fmaf(c, k4.z, y4.z); a.w = fmaf(c, k4.w, y4.w);
                    *reinterpret_cast<float4*>(&sYI[f]) = a;
                } else {
                    const float sx = 1.0f / 6.0f;
                    y4.x = fmaf(sx, ks0, y4.x); y4.y = fmaf(sx, ks1, y4.y);
                    y4.z = fmaf(sx, ks2, y4.z); y4.w = fmaf(sx, ks3, y4.w);
                    *reinterpret_cast<float4*>(&sY[f]) = y4;
                }
            }
            __syncthreads();
        }
    }

    // ---- decoder + sigmoid (rank 0 CTA) ----
    if (rank == 0 && tid < 32) {
        float acc = db[0];
        #pragma unroll 8
        for (int r = 0; r < 64; ++r) acc = fmaf(dW[r], sY[r * 32 + tid], acc);
        out[bbase + tid] = __fdividef(1.0f, 1.0f + __expf(-acc));
    }
}

extern "C" void kernel_launch(void* const* d_in, const int* in_sizes, int n_in,
                              void* d_out, int out_size) {
    (void)in_sizes; (void)n_in; (void)out_size;
    const float* xs  = (const float*)d_in[1];
    const float* eW0 = (const float*)d_in[2];
    const float* eb0 = (const float*)d_in[3];
    const float* eW1 = (const float*)d_in[4];
    const float* eb1 = (const float*)d_in[5];
    const float* eW2 = (const float*)d_in[6];
    const float* eb2 = (const float*)d_in[7];
    const float* vW0 = (const float*)d_in[8];
    const float* vb0 = (const float*)d_in[9];
    const float* vW1 = (const float*)d_in[10];
    const float* vb1 = (const float*)d_in[11];
    const float* vW2 = (const float*)d_in[12];
    const float* vb2 = (const float*)d_in[13];
    const float* dW  = (const float*)d_in[14];
    const float* db  = (const float*)d_in[15];
    float* out = (float*)d_out;

    cudaFuncSetAttribute(ncde_kernel, cudaFuncAttributeMaxDynamicSharedMemorySize, SMEM_BYTES);

    cudaLaunchConfig_t cfg = {};
    cfg.gridDim  = dim3(128, 1, 1);
    cfg.blockDim = dim3(512, 1, 1);
    cfg.dynamicSmemBytes = SMEM_BYTES;
    cfg.stream = 0;
    cudaLaunchAttribute attrs[1];
    attrs[0].id = cudaLaunchAttributeClusterDimension;
    attrs[0].val.clusterDim.x = 8;
    attrs[0].val.clusterDim.y = 1;
    attrs[0].val.clusterDim.z = 1;
    cfg.attrs = attrs;
    cfg.numAttrs = 1;

    cudaLaunchKernelEx(&cfg, ncde_kernel,
                       xs, eW0, eb0, eW1, eb1, eW2, eb2,
                       vW0, vb0, vW1, vb1, vW2, vb2, dW, db, out);
}

// round 11
// speedup vs baseline: 1.9073x; 1.1086x over previous
#include <cuda_runtime.h>
#include <cuda_bf16.h>
#include <cstdint>
#include <cstddef>

// ---------------------------------------------------------------------------
// Neural CDE classifier, ONE persistent clustered kernel + warp-level bf16
// mma.sync (3-pass hi/lo split ~ fp32 accuracy) for the big vf GEMM.
// R11: per-substep cluster barriers replaced by st.async + mbarrier
// transaction counting (expect_tx/complete_tx). No CCTL.IVALL, sleep-based
// waits, no aligned convergence. xs prefetched 2 steps ahead.
// grid = 128 CTAs = 16 clusters x 8, 512 thr/CTA, 1 CTA/SM.
// ---------------------------------------------------------------------------

typedef unsigned long long ull;

namespace {
constexpr int NSTEPS = 2047;
constexpr int KP2 = 272;   // A-operand padded row stride in BYTES (136 bf16)

// byte offsets in dynamic smem
constexpr int SB_AH = 0;        // 69632  W2 hi bf16 [256][136]
constexpr int SB_AL = 69632;    // 69632  W2 lo bf16 [256][136]
constexpr int SB_PK = 139264;   // 18432  h1 packed u32 (hi|lo) [128 k][36]
constexpr int SB_W1 = 157696;   // 8192   fp32 W1 slice [16][128]
constexpr int SB_W0 = 165888;   // 4096   fp32 W0 slice [16][64]
constexpr int SB_B0 = 169984;   // 64
constexpr int SB_B1 = 170048;   // 64
constexpr int SB_Y  = 170112;   // 8192   y   [64][32] fp32
constexpr int SB_YIN= 178304;   // 8192   yin
constexpr int SB_KC = 186496;   // 8192   k   [64][32]
constexpr int SB_H0 = 194688;   // 16384  h0  [128][32] fp32
constexpr int SB_DX = 211072;   // 4224   dx  [32][33] fp32
constexpr int SB_KP = 215296;   // 2048   k partials [16 warp][32 b]
constexpr int SB_MB = 217344;   // 24     3 mbarriers (h0, h1, k)
constexpr int SMEM_BYTES = 217376;

constexpr uint32_t TX_H0 = 16384;  // bytes/substep arriving at each CTA's h0 bar
constexpr uint32_t TX_H1 = 16384;
constexpr uint32_t TX_K  = 8192;
}

__device__ __forceinline__ uint32_t s2u(const void* p) {
    return (uint32_t)__cvta_generic_to_shared(p);
}
__device__ __forceinline__ uint32_t mapa_u(uint32_t laddr, int rank) {
    uint32_t r;
    asm("mapa.shared::cluster.u32 %0, %1, %2;" : "=r"(r) : "r"(laddr), "r"(rank));
    return r;
}
__device__ __forceinline__ void sta_f4(uint32_t raddr, uint32_t rmbar,
                                       float a, float b, float c, float d) {
    asm volatile(
        "st.async.shared::cluster.mbarrier::complete_tx::bytes.v4.f32 "
        "[%0], {%1,%2,%3,%4}, [%5];"
        :: "r"(raddr), "f"(a), "f"(b), "f"(c), "f"(d), "r"(rmbar) : "memory");
}
__device__ __forceinline__ void sta_u4(uint32_t raddr, uint32_t rmbar,
                                       uint32_t a, uint32_t b, uint32_t c, uint32_t d) {
    asm volatile(
        "st.async.shared::cluster.mbarrier::complete_tx::bytes.v4.b32 "
        "[%0], {%1,%2,%3,%4}, [%5];"
        :: "r"(raddr), "r"(a), "r"(b), "r"(c), "r"(d), "r"(rmbar) : "memory");
}
__device__ __forceinline__ void mbar_init(uint32_t mbar, uint32_t cnt) {
    asm volatile("mbarrier.init.shared.b64 [%0], %1;" :: "r"(mbar), "r"(cnt) : "memory");
}
__device__ __forceinline__ void mbar_expect(uint32_t mbar, uint32_t bytes) {
    asm volatile("mbarrier.arrive.expect_tx.shared.b64 _, [%0], %1;"
                 :: "r"(mbar), "r"(bytes) : "memory");
}
__device__ __forceinline__ void mbar_wait(uint32_t mbar, uint32_t parity) {
    asm volatile(
        "{\n\t.reg .pred P;\n\t"
        "WL_%=:\n\t"
        "mbarrier.try_wait.parity.acquire.cluster.shared::cta.b64 P, [%0], %1, 0x989680;\n\t"
        "@!P bra WL_%=;\n\t}"
        :: "r"(mbar), "r"(parity) : "memory");
}
__device__ __forceinline__ void cluster_sync_() {
    asm volatile("barrier.cluster.arrive.aligned;" ::: "memory");
    asm volatile("barrier.cluster.wait.aligned;" ::: "memory");
}
__device__ __forceinline__ uint32_t prmt(uint32_t a, uint32_t b, uint32_t sel) {
    uint32_t d;
    asm("prmt.b32 %0, %1, %2, %3;" : "=r"(d) : "r"(a), "r"(b), "r"(sel));
    return d;
}
__device__ __forceinline__ float tanh_f(float x) {
    float ax = fabsf(x);
    float e  = __expf(-2.0f * ax);
    float r  = __fdividef(1.0f - e, 1.0f + e);
    return copysignf(r, x);
}
__device__ __forceinline__ float gelu_f(float x) {
    float x3 = x * x * x;
    float t  = tanh_f(0.7978845608028654f * fmaf(0.044715f, x3, x));
    return 0.5f * x * (1.0f + t);
}
__device__ __forceinline__ void ldsm4(uint32_t (&r)[4], uint32_t addr) {
    asm volatile("ldmatrix.sync.aligned.m8n8.x4.shared.b16 {%0,%1,%2,%3}, [%4];"
                 : "=r"(r[0]), "=r"(r[1]), "=r"(r[2]), "=r"(r[3]) : "r"(addr));
}
__device__ __forceinline__ void mma16816(float (&c)[4], const uint32_t (&a)[4],
                                         uint32_t b0, uint32_t b1) {
    asm volatile(
        "mma.sync.aligned.m16n8k16.row.col.f32.bf16.bf16.f32 "
        "{%0,%1,%2,%3}, {%4,%5,%6,%7}, {%8,%9}, {%0,%1,%2,%3};"
        : "+f"(c[0]), "+f"(c[1]), "+f"(c[2]), "+f"(c[3])
        : "r"(a[0]), "r"(a[1]), "r"(a[2]), "r"(a[3]), "r"(b0), "r"(b1));
}

__global__ void __launch_bounds__(512, 1)
ncde_kernel(const float* __restrict__ xs,
            const float* __restrict__ eW0, const float* __restrict__ eb0,
            const float* __restrict__ eW1, const float* __restrict__ eb1,
            const float* __restrict__ eW2, const float* __restrict__ eb2,
            const float* __restrict__ vW0, const float* __restrict__ vb0,
            const float* __restrict__ vW1, const float* __restrict__ vb1,
            const float* __restrict__ vW2, const float* __restrict__ vb2,
            const float* __restrict__ dW,  const float* __restrict__ db,
            float* __restrict__ out)
{
    extern __shared__ char smc[];
    const int tid   = threadIdx.x;
    const int lane  = tid & 31;
    const int wid   = tid >> 5;          // 0..15
    const int rank  = blockIdx.x & 7;
    const int bbase = (blockIdx.x >> 3) * 32;

    float* sW1 = (float*)(smc + SB_W1);
    float* sW0 = (float*)(smc + SB_W0);
    float* sB0 = (float*)(smc + SB_B0);
    float* sB1 = (float*)(smc + SB_B1);
    float* sY  = (float*)(smc + SB_Y);
    float* sYI = (float*)(smc + SB_YIN);
    float* sKC = (float*)(smc + SB_KC);
    float* sH0 = (float*)(smc + SB_H0);
    float* sDX = (float*)(smc + SB_DX);
    float* sKP = (float*)(smc + SB_KP);
    const uint32_t* sPK = (const uint32_t*)(smc + SB_PK);

    const uint32_t smem_u = s2u(smc);
    const uint32_t mbH0 = smem_u + SB_MB;
    const uint32_t mbH1 = smem_u + SB_MB + 8;
    const uint32_t mbK  = smem_u + SB_MB + 16;

    if (tid == 0) {
        mbar_init(mbH0, 1);
        mbar_init(mbH1, 1);
        mbar_init(mbK, 1);
    }

    // per-rank DSMEM address deltas (mapa is affine in the local address)
    uint32_t rdelta[8];
    #pragma unroll
    for (int r = 0; r < 8; ++r) rdelta[r] = mapa_u(smem_u, r) - smem_u;

    // xs mapping: thread owns (b = tid>>4, d = 2*(tid&15), +1)
    const int xb  = tid >> 4;
    const int xd2 = tid & 15;
    const float* xsrow = xs + (size_t)(bbase + xb) * 2048 * 32 + xd2 * 2;

    float xc0, xc1;
    {
        float2 v = *reinterpret_cast<const float2*>(xsrow);
        xc0 = v.x; xc1 = v.y;
        sKC[(2 * xd2) * 32 + xb]     = v.x;   // stage xs0 d-major for encoder
        sKC[(2 * xd2 + 1) * 32 + xb] = v.y;
    }

    // ---- encoder weights transposed into A scratch (floats) ----
    float* sE0 = (float*)(smc + SB_AH);          // [32][128]
    float* sE1 = sE0 + 4096;                     // [128][128]
    float* sE2 = sE0 + 20480;                    // [128][64]
    float* sEH = sE0 + 28672;                    // [128][32]
    for (int i = tid; i < 4096;  i += 512) { int r = i & 127, kk = i >> 7; sE0[i] = eW0[r * 32  + kk]; }
    for (int i = tid; i < 16384; i += 512) { int r = i & 127, kk = i >> 7; sE1[i] = eW1[r * 128 + kk]; }
    for (int i = tid; i < 8192;  i += 512) { int r = i & 63,  kk = i >> 6; sE2[i] = eW2[r * 128 + kk]; }
    __syncthreads();

    // ---- encoder (replicated per CTA): sKC(xs0) -> sH0 -> sEH -> sY ----
    {
        int b = lane, rbase = wid * 8;
        float acc[8];
        #pragma unroll
        for (int j = 0; j < 8; ++j) acc[j] = eb0[rbase + j];
        for (int kk = 0; kk < 32; ++kk) {
            float x = sKC[kk * 32 + b];
            #pragma unroll
            for (int j = 0; j < 8; ++j) acc[j] = fmaf(sE0[kk * 128 + rbase + j], x, acc[j]);
        }
        #pragma unroll
        for (int j = 0; j < 8; ++j) sH0[(rbase + j) * 32 + b] = fmaxf(acc[j], 0.0f);
    }
    __syncthreads();
    {
        int b = lane, rbase = wid * 8;
        float acc[8];
        #pragma unroll
        for (int j = 0; j < 8; ++j) acc[j] = eb1[rbase + j];
        for (int kk = 0; kk < 128; ++kk) {
            float x = sH0[kk * 32 + b];
            #pragma unroll
            for (int j = 0; j < 8; ++j) acc[j] = fmaf(sE1[kk * 128 + rbase + j], x, acc[j]);
        }
        #pragma unroll
        for (int j = 0; j < 8; ++j) sEH[(rbase + j) * 32 + b] = fmaxf(acc[j], 0.0f);
    }
    __syncthreads();
    {
        int b = lane, rbase = wid * 4;
        float acc[4];
        #pragma unroll
        for (int j = 0; j < 4; ++j) acc[j] = eb2[rbase + j];
        for (int kk = 0; kk < 128; ++kk) {
            float x = sEH[kk * 32 + b];
            #pragma unroll
            for (int j = 0; j < 4; ++j) acc[j] = fmaf(sE2[kk * 64 + rbase + j], x, acc[j]);
        }
        #pragma unroll
        for (int j = 0; j < 4; ++j) sY[(rbase + j) * 32 + b] = acc[j];
    }
    __syncthreads();

    // ---- build static bf16 hi/lo A operand (overwrites encoder scratch) ----
    for (int i = tid; i < 32768; i += 512) {
        int m = i >> 7, k = i & 127;
        float w = vW2[(size_t)(rank * 256 + m) * 128 + k];
        __nv_bfloat16 hb = __float2bfloat16(w);
        float hf = __bfloat162float(hb);
        __nv_bfloat16 lb = __float2bfloat16(w - hf);
        *(__nv_bfloat16*)(smc + SB_AH + m * KP2 + k * 2) = hb;
        *(__nv_bfloat16*)(smc + SB_AL + m * KP2 + k * 2) = lb;
    }
    for (int i = tid; i < 2048; i += 512) {
        int kk = i & 127, r = i >> 7;
        sW1[i] = vW1[(rank * 16 + r) * 128 + kk];
    }
    for (int i = tid; i < 1024; i += 512) {
        int kk = i & 63, r = i >> 6;
        sW0[i] = vW0[(rank * 16 + r) * 64 + kk];
    }
    if (tid < 16)      sB0[tid]      = vb0[rank * 16 + tid];
    else if (tid < 32) sB1[tid - 16] = vb1[rank * 16 + tid - 16];

    // post expects for the first substep, then one cluster barrier so all
    // inits/weights are visible before any st.async lands anywhere
    __syncthreads();
    if (tid == 0) {
        mbar_expect(mbH0, TX_H0);
        mbar_expect(mbH1, TX_H1);
        mbar_expect(mbK,  TX_K);
    }
    cluster_sync_();

    // ---- per-thread invariants ----
    const int g  = lane >> 2;           // mma group id
    const int tg = lane & 3;            // thread in group
    const float b0s = sB0[wid];
    const float b1s = sB1[wid];
    const uint32_t aH0 = s2u(&sH0[(rank * 16 + wid) * 32 + lane]);   // lane%4==0 stores v4
    const int kg = rank * 16 + wid;     // global k row produced by this thread in L1
    const uint32_t aPK = smem_u + SB_PK + (uint32_t)(kg * 36 + lane) * 4;

    // A ldmatrix addresses (per k-step add 32B)
    const uint32_t aAH = smem_u + SB_AH + (uint32_t)(wid * 16 + (lane & 15)) * KP2 + (lane >> 4) * 16;
    const uint32_t aAL = aAH + (SB_AL - SB_AH);

    // B fragment source (packed): per-thread base index into sPK
    const uint32_t* pkT = sPK + tg * 2 * 36 + g;

    // epilogue invariants
    const float b2a = vb2[rank * 256 + wid * 16 + g];
    const float b2b = vb2[rank * 256 + wid * 16 + g + 8];
    const int d0 = (wid & 1) * 16 + g;
    uint32_t aKC = 0;
    if (wid < 8) aKC = s2u(&sKC[(rank * 8 + wid) * 32 + lane]);

    uint32_t ph = 0;

    // xs prefetch, 2 steps deep
    float2 xnA = *reinterpret_cast<const float2*>(xsrow + (size_t)1 * 32);
    float2 xnB = *reinterpret_cast<const float2*>(xsrow + (size_t)2 * 32);

    // ---- main RK4 scan ----
    for (int t = 0; t < NSTEPS; ++t) {
        float2 xn = xnA;
        {
            int tn = (t + 3 <= 2047) ? (t + 3) : 2047;
            xnA = xnB;
            xnB = *reinterpret_cast<const float2*>(xsrow + (size_t)tn * 32);
        }
        float ks0, ks1, ks2, ks3;

        #pragma unroll
        for (int s = 0; s < 4; ++s) {
            const float* yin = (s == 0) ? sY : sYI;

            // ---- L0: h0[wid][lane] = gelu(W0row . yin + b0), wide async push
            {
                float a = b0s;
                const float* wrow = sW0 + wid * 64;
                #pragma unroll
                for (int k4 = 0; k4 < 16; ++k4) {
                    float4 w4 = *reinterpret_cast<const float4*>(wrow + k4 * 4);
                    a = fmaf(w4.x, yin[(k4 * 4 + 0) * 32 + lane], a);
                    a = fmaf(w4.y, yin[(k4 * 4 + 1) * 32 + lane], a);
                    a = fmaf(w4.z, yin[(k4 * 4 + 2) * 32 + lane], a);
                    a = fmaf(w4.w, yin[(k4 * 4 + 3) * 32 + lane], a);
                }
                a = gelu_f(a);
                float a1 = __shfl_down_sync(0xffffffffu, a, 1);
                float a2 = __shfl_down_sync(0xffffffffu, a, 2);
                float a3 = __shfl_down_sync(0xffffffffu, a, 3);
                if ((lane & 3) == 0) {
                    #pragma unroll
                    for (int r = 0; r < 8; ++r)
                        sta_f4(aH0 + rdelta[r], mbH0 + rdelta[r], a, a1, a2, a3);
                }
            }
            if (s == 0) {
                float dd0 = xn.x - xc0, dd1 = xn.y - xc1;
                xc0 = xn.x; xc1 = xn.y;
                sDX[(2 * xd2) * 33 + xb]     = dd0;
                sDX[(2 * xd2 + 1) * 33 + xb] = dd1;
            }
            mbar_wait(mbH0, ph);   // h0 complete everywhere (tx-counted)
            __syncthreads();       // orders dx writes vs epilogue reads

            // ---- L1: h1[kg][lane] -> packed (hi|lo) u32, wide async push ----
            {
                float a = b1s;
                const float* wrow = sW1 + wid * 128;
                #pragma unroll 8
                for (int k4 = 0; k4 < 32; ++k4) {
                    float4 w4 = *reinterpret_cast<const float4*>(wrow + k4 * 4);
                    a = fmaf(w4.x, sH0[(k4 * 4 + 0) * 32 + lane], a);
                    a = fmaf(w4.y, sH0[(k4 * 4 + 1) * 32 + lane], a);
                    a = fmaf(w4.z, sH0[(k4 * 4 + 2) * 32 + lane], a);
                    a = fmaf(w4.w, sH0[(k4 * 4 + 3) * 32 + lane], a);
                }
                a = gelu_f(a);
                __nv_bfloat16 hb = __float2bfloat16(a);
                float hf = __bfloat162float(hb);
                __nv_bfloat16 lb = __float2bfloat16(a - hf);
                uint32_t w = (uint32_t)reinterpret_cast<unsigned short&>(hb) |
                             ((uint32_t)reinterpret_cast<unsigned short&>(lb) << 16);
                uint32_t w1 = __shfl_down_sync(0xffffffffu, w, 1);
                uint32_t w2 = __shfl_down_sync(0xffffffffu, w, 2);
                uint32_t w3 = __shfl_down_sync(0xffffffffu, w, 3);
                if ((lane & 3) == 0) {
                    #pragma unroll
                    for (int r = 0; r < 8; ++r)
                        sta_u4(aPK + rdelta[r], mbH1 + rdelta[r], w, w1, w2, w3);
                }
            }
            mbar_wait(mbH1, ph);   // packed B operand complete everywhere

            // ---- W2 GEMM via mma.sync, 3-pass bf16 hi/lo ----
            float acc[4][4];
            #pragma unroll
            for (int nt = 0; nt < 4; ++nt)
                #pragma unroll
                for (int i = 0; i < 4; ++i) acc[nt][i] = 0.0f;

            #pragma unroll
            for (int kk = 0; kk < 8; ++kk) {
                uint32_t ah[4], al[4];
                ldsm4(ah, aAH + kk * 32);
                ldsm4(al, aAL + kk * 32);
                const uint32_t* pkk = pkT + kk * 16 * 36;
                #pragma unroll
                for (int nt = 0; nt < 4; ++nt) {
                    uint32_t w0 = pkk[nt * 8];
                    uint32_t w1 = pkk[nt * 8 + 36];
                    uint32_t w8 = pkk[nt * 8 + 8 * 36];
                    uint32_t w9 = pkk[nt * 8 + 9 * 36];
                    uint32_t bh0 = prmt(w0, w1, 0x5410u);
                    uint32_t bl0 = prmt(w0, w1, 0x7632u);
                    uint32_t bh1 = prmt(w8, w9, 0x5410u);
                    uint32_t bl1 = prmt(w8, w9, 0x7632u);
                    mma16816(acc[nt], ah, bh0, bh1);   // hi * hi
                    mma16816(acc[nt], ah, bl0, bl1);   // hi * lo
                    mma16816(acc[nt], al, bh0, bh1);   // lo * hi
                }
            }

            // ---- epilogue: tanh(+bias) * dx, reduce over d ----
            {
                float p[8];
                #pragma unroll
                for (int nt = 0; nt < 4; ++nt) {
                    int b0i = nt * 8 + tg * 2;
                    float u00 = tanh_f(acc[nt][0] + b2a);
                    float u01 = tanh_f(acc[nt][1] + b2a);
                    float u10 = tanh_f(acc[nt][2] + b2b);
                    float u11 = tanh_f(acc[nt][3] + b2b);
                    p[nt * 2 + 0] = fmaf(u00, sDX[d0 * 33 + b0i],
                                         u10 * sDX[(d0 + 8) * 33 + b0i]);
                    p[nt * 2 + 1] = fmaf(u01, sDX[d0 * 33 + b0i + 1],
                                         u11 * sDX[(d0 + 8) * 33 + b0i + 1]);
                }
                #pragma unroll
                for (int m = 4; m <= 16; m <<= 1)
                    #pragma unroll
                    for (int i = 0; i < 8; ++i)
                        p[i] += __shfl_xor_sync(0xffffffffu, p[i], m);
                if (lane < 4) {
                    #pragma unroll
                    for (int nt = 0; nt < 4; ++nt) {
                        float2 v = make_float2(p[nt * 2], p[nt * 2 + 1]);
                        *reinterpret_cast<float2*>(&sKP[wid * 32 + nt * 8 + tg * 2]) = v;
                    }
                }
            }
            __syncthreads();
            if (wid < 8) {
                float v = sKP[(2 * wid) * 32 + lane] + sKP[(2 * wid + 1) * 32 + lane];
                float v1 = __shfl_down_sync(0xffffffffu, v, 1);
                float v2 = __shfl_down_sync(0xffffffffu, v, 2);
                float v3 = __shfl_down_sync(0xffffffffu, v, 3);
                if ((lane & 3) == 0) {
                    #pragma unroll
                    for (int r = 0; r < 8; ++r)
                        sta_f4(aKC + rdelta[r], mbK + rdelta[r], v, v1, v2, v3);
                }
            }
            mbar_wait(mbK, ph);    // k complete everywhere

            // ---- RK4 combine (thread owns y elements [tid*4, tid*4+4)) ----
            {
                const int f = tid * 4;
                float4 k4 = *reinterpret_cast<float4*>(&sKC[f]);
                if (s == 0) {
                    ks0 = k4.x; ks1 = k4.y; ks2 = k4.z; ks3 = k4.w;
                } else {
                    const float w_s = (s == 3) ? 1.0f : 2.0f;
                    ks0 = fmaf(w_s, k4.x, ks0); ks1 = fmaf(w_s, k4.y, ks1);
                    ks2 = fmaf(w_s, k4.z, ks2); ks3 = fmaf(w_s, k4.w, ks3);
                }
                float4 y4 = *reinterpret_cast<float4*>(&sY[f]);
                if (s < 3) {
                    const float c = (s == 2) ? 1.0f : 0.5f;
                    float4 a;
                    a.x = fmaf(c, k4.x, y4.x); a.y = fmaf(c, k4.y, y4.y);
                    a.z = fmaf(c, k4.z, y4.z); a.w = fmaf(c, k4.w, y4.w);
                    *reinterpret_cast<float4*>(&sYI[f]) = a;
                } else {
                    const float sx = 1.0f / 6.0f;
                    y4.x = fmaf(sx, ks0, y4.x); y4.y = fmaf(sx, ks1, y4.y);
                    y4.z = fmaf(sx, ks2, y4.z); y4.w = fmaf(sx, ks3, y4.w);
                    *reinterpret_cast<float4*>(&sY[f]) = y4;
                }
            }
            __syncthreads();       // sYI/sY visible to all before next L0
            if (tid == 0) {        // arm barriers for the next substep
                mbar_expect(mbH0, TX_H0);
                mbar_expect(mbH1, TX_H1);
                mbar_expect(mbK,  TX_K);
            }
            ph ^= 1;
        }
    }

    // ---- decoder + sigmoid (rank 0 CTA) ----
    if (rank == 0 && tid < 32) {
        float acc = db[0];
        #pragma unroll 8
        for (int r = 0; r < 64; ++r) acc = fmaf(dW[r], sY[r * 32 + tid], acc);
        out[bbase + tid] = __fdividef(1.0f, 1.0f + __expf(-acc));
    }

    cluster_sync_();  // no CTA exits while peers could still address its smem
}

extern "C" void kernel_launch(void* const* d_in, const int* in_sizes, int n_in,
                              void* d_out, int out_size) {
    (void)in_sizes; (void)n_in; (void)out_size;
    const float* xs  = (const float*)d_in[1];
    const float* eW0 = (const float*)d_in[2];
    const float* eb0 = (const float*)d_in[3];
    const float* eW1 = (const float*)d_in[4];
    const float* eb1 = (const float*)d_in[5];
    const float* eW2 = (const float*)d_in[6];
    const float* eb2 = (const float*)d_in[7];
    const float* vW0 = (const float*)d_in[8];
    const float* vb0 = (const float*)d_in[9];
    const float* vW1 = (const float*)d_in[10];
    const float* vb1 = (const float*)d_in[11];
    const float* vW2 = (const float*)d_in[12];
    const float* vb2 = (const float*)d_in[13];
    const float* dW  = (const float*)d_in[14];
    const float* db  = (const float*)d_in[15];
    float* out = (float*)d_out;

    cudaFuncSetAttribute(ncde_kernel, cudaFuncAttributeMaxDynamicSharedMemorySize, SMEM_BYTES);

    cudaLaunchConfig_t cfg = {};
    cfg.gridDim  = dim3(128, 1, 1);
    cfg.blockDim = dim3(512, 1, 1);
    cfg.dynamicSmemBytes = SMEM_BYTES;
    cfg.stream = 0;
    cudaLaunchAttribute attrs[1];
    attrs[0].id = cudaLaunchAttributeClusterDimension;
    attrs[0].val.clusterDim.x = 8;
    attrs[0].val.clusterDim.y = 1;
    attrs[0].val.clusterDim.z = 1;
    cfg.attrs = attrs;
    cfg.numAttrs = 1;

    cudaLaunchKernelEx(&cfg, ncde_kernel,
                       xs, eW0, eb0, eW1, eb1, eW2, eb2,
                       vW0, vb0, vW1, vb1, vW2, vb2, dW, db, out);
}

// round 12
// speedup vs baseline: 1.9713x; 1.0336x over previous
#include <cuda_runtime.h>
#include <cuda_bf16.h>
#include <cstdint>
#include <cstddef>

// ---------------------------------------------------------------------------
// Neural CDE classifier, ONE persistent clustered kernel. bf16 mma.sync
// (3-pass hi/lo ~ fp32) for BOTH the L1 GEMM (pair-redundant, W1 sliced 64
// rows per CTA-pair member) and the big W2 GEMM (sliced 256 rows/CTA).
// Exchanges per substep: h0 packed allgather (16KB, st.async+mbar tx),
// h1 single-peer exchange (8KB), k allgather (8KB). y state in registers.
// grid = 128 CTAs = 16 clusters x 8, 512 thr/CTA, 1 CTA/SM.
// ---------------------------------------------------------------------------

typedef unsigned long long ull;

namespace {
constexpr int NSTEPS = 2047;
constexpr int KP2 = 272;        // A-operand row stride in BYTES (136 bf16)

// byte offsets in dynamic smem
constexpr int SB_AH  = 0;       // 69632  W2 hi bf16 [256][136]
constexpr int SB_AL  = 69632;   // 69632  W2 lo
constexpr int SB_W1H = 139264;  // 17408  W1-slice hi bf16 [64][136]
constexpr int SB_W1L = 156672;  // 17408  W1-slice lo
constexpr int SB_PK  = 174080;  // 18432  packed u32 (hi|lo) [128][36]: h0 then h1(own half)
constexpr int SB_PK2 = 192512;  // 8704   peer h1 half, packed u32 [64][34]
constexpr int SB_W0  = 201216;  // 4096   fp32 W0 slice [16][64]
constexpr int SB_YIN = 205312;  // 8192   yin/y [64][32] fp32 (KP aliases first 2048 B)
constexpr int SB_KC  = 213504;  // 8192   k [64][32] fp32
constexpr int SB_DX  = 221696;  // 4352   dx [32][34] fp32
constexpr int SB_MB  = 226048;  // 24     3 mbarriers (h0, h1pair, k)
constexpr int SMEM_BYTES = 226080;

constexpr uint32_t TX_H0 = 16384;
constexpr uint32_t TX_H1 = 8192;
constexpr uint32_t TX_K  = 8192;
}

__device__ __forceinline__ uint32_t s2u(const void* p) {
    return (uint32_t)__cvta_generic_to_shared(p);
}
__device__ __forceinline__ uint32_t mapa_u(uint32_t laddr, int rank) {
    uint32_t r;
    asm("mapa.shared::cluster.u32 %0, %1, %2;" : "=r"(r) : "r"(laddr), "r"(rank));
    return r;
}
__device__ __forceinline__ void sta_f4(uint32_t raddr, uint32_t rmbar,
                                       float a, float b, float c, float d) {
    asm volatile(
        "st.async.shared::cluster.mbarrier::complete_tx::bytes.v4.f32 "
        "[%0], {%1,%2,%3,%4}, [%5];"
        :: "r"(raddr), "f"(a), "f"(b), "f"(c), "f"(d), "r"(rmbar) : "memory");
}
__device__ __forceinline__ void sta_u4(uint32_t raddr, uint32_t rmbar,
                                       uint32_t a, uint32_t b, uint32_t c, uint32_t d) {
    asm volatile(
        "st.async.shared::cluster.mbarrier::complete_tx::bytes.v4.b32 "
        "[%0], {%1,%2,%3,%4}, [%5];"
        :: "r"(raddr), "r"(a), "r"(b), "r"(c), "r"(d), "r"(rmbar) : "memory");
}
__device__ __forceinline__ void sta_u2(uint32_t raddr, uint32_t rmbar, uint32_t a, uint32_t b) {
    ull v;
    asm("mov.b64 %0, {%1, %2};" : "=l"(v) : "r"(a), "r"(b));
    asm volatile(
        "st.async.shared::cluster.mbarrier::complete_tx::bytes.b64 [%0], %1, [%2];"
        :: "r"(raddr), "l"(v), "r"(rmbar) : "memory");
}
__device__ __forceinline__ void mbar_init(uint32_t mbar, uint32_t cnt) {
    asm volatile("mbarrier.init.shared.b64 [%0], %1;" :: "r"(mbar), "r"(cnt) : "memory");
}
__device__ __forceinline__ void mbar_expect(uint32_t mbar, uint32_t bytes) {
    asm volatile("mbarrier.arrive.expect_tx.shared.b64 _, [%0], %1;"
                 :: "r"(mbar), "r"(bytes) : "memory");
}
__device__ __forceinline__ void mbar_wait(uint32_t mbar, uint32_t parity) {
    asm volatile(
        "{\n\t.reg .pred P;\n\t"
        "WL_%=:\n\t"
        "mbarrier.try_wait.parity.acquire.cluster.shared::cta.b64 P, [%0], %1, 0x989680;\n\t"
        "@!P bra WL_%=;\n\t}"
        :: "r"(mbar), "r"(parity) : "memory");
}
__device__ __forceinline__ void cluster_sync_() {
    asm volatile("barrier.cluster.arrive.aligned;" ::: "memory");
    asm volatile("barrier.cluster.wait.aligned;" ::: "memory");
}
__device__ __forceinline__ uint32_t prmt(uint32_t a, uint32_t b, uint32_t sel) {
    uint32_t d;
    asm("prmt.b32 %0, %1, %2, %3;" : "=r"(d) : "r"(a), "r"(b), "r"(sel));
    return d;
}
__device__ __forceinline__ float tanh_f(float x) {
    float ax = fabsf(x);
    float e  = __expf(-2.0f * ax);
    float r  = __fdividef(1.0f - e, 1.0f + e);
    return copysignf(r, x);
}
__device__ __forceinline__ float gelu_f(float x) {
    float x3 = x * x * x;
    float t  = tanh_f(0.7978845608028654f * fmaf(0.044715f, x3, x));
    return 0.5f * x * (1.0f + t);
}
__device__ __forceinline__ uint32_t pack_hilo(float a) {
    __nv_bfloat16 hb = __float2bfloat16(a);
    float hf = __bfloat162float(hb);
    __nv_bfloat16 lb = __float2bfloat16(a - hf);
    return (uint32_t)reinterpret_cast<unsigned short&>(hb) |
           ((uint32_t)reinterpret_cast<unsigned short&>(lb) << 16);
}
__device__ __forceinline__ void ldsm4(uint32_t (&r)[4], uint32_t addr) {
    asm volatile("ldmatrix.sync.aligned.m8n8.x4.shared.b16 {%0,%1,%2,%3}, [%4];"
                 : "=r"(r[0]), "=r"(r[1]), "=r"(r[2]), "=r"(r[3]) : "r"(addr));
}
__device__ __forceinline__ void mma16816(float (&c)[4], const uint32_t (&a)[4],
                                         uint32_t b0, uint32_t b1) {
    asm volatile(
        "mma.sync.aligned.m16n8k16.row.col.f32.bf16.bf16.f32 "
        "{%0,%1,%2,%3}, {%4,%5,%6,%7}, {%8,%9}, {%0,%1,%2,%3};"
        : "+f"(c[0]), "+f"(c[1]), "+f"(c[2]), "+f"(c[3])
        : "r"(a[0]), "r"(a[1]), "r"(a[2]), "r"(a[3]), "r"(b0), "r"(b1));
}

__global__ void __launch_bounds__(512, 1)
ncde_kernel(const float* __restrict__ xs,
            const float* __restrict__ eW0, const float* __restrict__ eb0,
            const float* __restrict__ eW1, const float* __restrict__ eb1,
            const float* __restrict__ eW2, const float* __restrict__ eb2,
            const float* __restrict__ vW0, const float* __restrict__ vb0,
            const float* __restrict__ vW1, const float* __restrict__ vb1,
            const float* __restrict__ vW2, const float* __restrict__ vb2,
            const float* __restrict__ dW,  const float* __restrict__ db,
            float* __restrict__ out)
{
    extern __shared__ char smc[];
    const int tid   = threadIdx.x;
    const int lane  = tid & 31;
    const int wid   = tid >> 5;          // 0..15
    const int rank  = blockIdx.x & 7;
    const int half_ = rank & 1;
    const int bbase = (blockIdx.x >> 3) * 32;

    float* sW0 = (float*)(smc + SB_W0);
    float* sYI = (float*)(smc + SB_YIN);
    float* sKC = (float*)(smc + SB_KC);
    float* sDX = (float*)(smc + SB_DX);
    float* sKP = (float*)(smc + SB_YIN);            // aliases sYI[0:512]
    uint32_t* sPKw = (uint32_t*)(smc + SB_PK);

    const uint32_t smem_u = s2u(smc);
    const uint32_t mbH0 = smem_u + SB_MB;
    const uint32_t mbH1 = smem_u + SB_MB + 8;
    const uint32_t mbK  = smem_u + SB_MB + 16;

    if (tid == 0) {
        mbar_init(mbH0, 1);
        mbar_init(mbH1, 1);
        mbar_init(mbK, 1);
    }

    // per-rank DSMEM address deltas (mapa is affine in the local address)
    uint32_t rdelta[8];
    #pragma unroll
    for (int r = 0; r < 8; ++r) rdelta[r] = mapa_u(smem_u, r) - smem_u;
    const uint32_t pdelta = rdelta[rank ^ 1];

    // xs mapping: thread owns (b = tid>>4, d = 2*(tid&15), +1)
    const int xb  = tid >> 4;
    const int xd2 = tid & 15;
    const float* xsrow = xs + (size_t)(bbase + xb) * 2048 * 32 + xd2 * 2;

    float xc0, xc1;
    {
        float2 v = *reinterpret_cast<const float2*>(xsrow);
        xc0 = v.x; xc1 = v.y;
        sKC[(2 * xd2) * 32 + xb]     = v.x;   // stage xs0 d-major for encoder
        sKC[(2 * xd2 + 1) * 32 + xb] = v.y;
    }

    // ---- encoder weights transposed into W2 scratch region (floats) ----
    float* sE0 = (float*)(smc + SB_AH);          // [32][128]
    float* sE1 = sE0 + 4096;                     // [128][128]
    float* sE2 = sE0 + 20480;                    // [128][64]
    float* sEH = sE0 + 28672;                    // [128][32]
    float* sH0e = (float*)(smc + SB_PK);         // [128][32] encoder hidden1
    for (int i = tid; i < 4096;  i += 512) { int r = i & 127, kk = i >> 7; sE0[i] = eW0[r * 32  + kk]; }
    for (int i = tid; i < 16384; i += 512) { int r = i & 127, kk = i >> 7; sE1[i] = eW1[r * 128 + kk]; }
    for (int i = tid; i < 8192;  i += 512) { int r = i & 63,  kk = i >> 6; sE2[i] = eW2[r * 128 + kk]; }
    __syncthreads();

    // ---- encoder (replicated per CTA): sKC(xs0) -> sH0e -> sEH -> sYI ----
    {
        int b = lane, rbase = wid * 8;
        float acc[8];
        #pragma unroll
        for (int j = 0; j < 8; ++j) acc[j] = eb0[rbase + j];
        for (int kk = 0; kk < 32; ++kk) {
            float x = sKC[kk * 32 + b];
            #pragma unroll
            for (int j = 0; j < 8; ++j) acc[j] = fmaf(sE0[kk * 128 + rbase + j], x, acc[j]);
        }
        #pragma unroll
        for (int j = 0; j < 8; ++j) sH0e[(rbase + j) * 32 + b] = fmaxf(acc[j], 0.0f);
    }
    __syncthreads();
    {
        int b = lane, rbase = wid * 8;
        float acc[8];
        #pragma unroll
        for (int j = 0; j < 8; ++j) acc[j] = eb1[rbase + j];
        for (int kk = 0; kk < 128; ++kk) {
            float x = sH0e[kk * 32 + b];
            #pragma unroll
            for (int j = 0; j < 8; ++j) acc[j] = fmaf(sE1[kk * 128 + rbase + j], x, acc[j]);
        }
        #pragma unroll
        for (int j = 0; j < 8; ++j) sEH[(rbase + j) * 32 + b] = fmaxf(acc[j], 0.0f);
    }
    __syncthreads();
    {
        int b = lane, rbase = wid * 4;
        float acc[4];
        #pragma unroll
        for (int j = 0; j < 4; ++j) acc[j] = eb2[rbase + j];
        for (int kk = 0; kk < 128; ++kk) {
            float x = sEH[kk * 32 + b];
            #pragma unroll
            for (int j = 0; j < 4; ++j) acc[j] = fmaf(sE2[kk * 64 + rbase + j], x, acc[j]);
        }
        #pragma unroll
        for (int j = 0; j < 4; ++j) sYI[(rbase + j) * 32 + b] = acc[j];
    }
    __syncthreads();

    // ---- build static bf16 hi/lo operands (overwrites encoder scratch) ----
    for (int i = tid; i < 32768; i += 512) {        // W2 slice [256 m][128 k]
        int m = i >> 7, k = i & 127;
        float w = vW2[(size_t)(rank * 256 + m) * 128 + k];
        __nv_bfloat16 hb = __float2bfloat16(w);
        float hf = __bfloat162float(hb);
        __nv_bfloat16 lb = __float2bfloat16(w - hf);
        *(__nv_bfloat16*)(smc + SB_AH + m * KP2 + k * 2) = hb;
        *(__nv_bfloat16*)(smc + SB_AL + m * KP2 + k * 2) = lb;
    }
    for (int i = tid; i < 8192; i += 512) {         // W1 slice [64 m][128 k]
        int m = i >> 7, k = i & 127;
        float w = vW1[(size_t)(half_ * 64 + m) * 128 + k];
        __nv_bfloat16 hb = __float2bfloat16(w);
        float hf = __bfloat162float(hb);
        __nv_bfloat16 lb = __float2bfloat16(w - hf);
        *(__nv_bfloat16*)(smc + SB_W1H + m * KP2 + k * 2) = hb;
        *(__nv_bfloat16*)(smc + SB_W1L + m * KP2 + k * 2) = lb;
    }
    for (int i = tid; i < 1024; i += 512) {         // W0 slice fp32 [16][64]
        int kk = i & 63, r = i >> 6;
        sW0[i] = vW0[(rank * 16 + r) * 64 + kk];
    }

    __syncthreads();
    if (tid == 0) {
        mbar_expect(mbH0, TX_H0);
        mbar_expect(mbH1, TX_H1);
        mbar_expect(mbK,  TX_K);
    }
    cluster_sync_();

    // ---- per-thread invariants ----
    const int g  = lane >> 2;
    const int tg = lane & 3;
    const float b0s = vb0[rank * 16 + wid];

    // L0 push dest (own row kg, all ranks); quad-leader pushes v4
    const uint32_t aPK0 = smem_u + SB_PK + (uint32_t)(((rank * 16 + wid) * 36) + lane) * 4;

    // L1-MMA: warp tile (mtile = wid>>2, ntile = wid&3)
    const int mtile = wid >> 2;
    const int ntl1  = wid & 3;
    const float b1a = vb1[half_ * 64 + mtile * 16 + (lane >> 2)];
    const float b1b = vb1[half_ * 64 + mtile * 16 + (lane >> 2) + 8];
    const uint32_t aW1H = smem_u + SB_W1H + (uint32_t)(mtile * 16 + (lane & 15)) * KP2 + (lane >> 4) * 16;
    const uint32_t aW1L = aW1H + (SB_W1L - SB_W1H);
    const uint32_t* pkL1 = sPKw + tg * 72 + ntl1 * 8 + g;

    // h1 output (own half in PK, peer copy to PK2)
    const int m0r   = mtile * 16 + (lane >> 2);     // local m row (0..63)
    const int b0c   = ntl1 * 8 + tg * 2;
    ull* h1loc0 = (ull*)(sPKw + (half_ * 64 + m0r) * 36 + b0c);
    ull* h1loc1 = (ull*)(sPKw + (half_ * 64 + m0r + 8) * 36 + b0c);
    const uint32_t aP2a = smem_u + SB_PK2 + (uint32_t)(m0r * 34 + b0c) * 4;
    const uint32_t aP2b = aP2a + 8 * 34 * 4;

    // W2-MMA invariants
    const uint32_t aAH = smem_u + SB_AH + (uint32_t)(wid * 16 + (lane & 15)) * KP2 + (lane >> 4) * 16;
    const uint32_t aAL = aAH + (SB_AL - SB_AH);
    const uint32_t* pkOwn  = sPKw + half_ * 4 * 576 + tg * 72 + g;
    const uint32_t* pkPeer = (const uint32_t*)(smc + SB_PK2) + tg * 68 + g;
    const int kkPeerBase = (1 - half_) * 4;         // A k-step base for peer half

    // epilogue invariants
    const float b2a = vb2[rank * 256 + wid * 16 + g];
    const float b2b = vb2[rank * 256 + wid * 16 + g + 8];
    const int d0 = (wid & 1) * 16 + g;
    uint32_t aKC = 0;
    if (wid < 8) aKC = s2u(&sKC[(rank * 8 + wid) * 32 + lane]);

    // persistent y state (thread owns elements [tid*4, tid*4+4))
    float y0 = sYI[tid * 4 + 0], y1 = sYI[tid * 4 + 1];
    float y2 = sYI[tid * 4 + 2], y3 = sYI[tid * 4 + 3];

    uint32_t ph = 0;

    float2 xnA = *reinterpret_cast<const float2*>(xsrow + (size_t)1 * 32);
    float2 xnB = *reinterpret_cast<const float2*>(xsrow + (size_t)2 * 32);

    // ---- main RK4 scan ----
    for (int t = 0; t < NSTEPS; ++t) {
        float2 xn = xnA;
        {
            int tn = (t + 3 <= 2047) ? (t + 3) : 2047;
            xnA = xnB;
            xnB = *reinterpret_cast<const float2*>(xsrow + (size_t)tn * 32);
        }
        float ks0, ks1, ks2, ks3;

        #pragma unroll
        for (int s = 0; s < 4; ++s) {
            // ---- L0: h0[wid][lane] = gelu(W0row . yin + b0), packed push ----
            {
                float a0 = b0s, a1 = 0.0f, a2 = 0.0f, a3 = 0.0f;
                const float* wrow = sW0 + wid * 64;
                #pragma unroll
                for (int k4 = 0; k4 < 16; ++k4) {
                    float4 w4 = *reinterpret_cast<const float4*>(wrow + k4 * 4);
                    a0 = fmaf(w4.x, sYI[(k4 * 4 + 0) * 32 + lane], a0);
                    a1 = fmaf(w4.y, sYI[(k4 * 4 + 1) * 32 + lane], a1);
                    a2 = fmaf(w4.z, sYI[(k4 * 4 + 2) * 32 + lane], a2);
                    a3 = fmaf(w4.w, sYI[(k4 * 4 + 3) * 32 + lane], a3);
                }
                float a = (a0 + a1) + (a2 + a3);
                uint32_t w = pack_hilo(gelu_f(a));
                uint32_t w1 = __shfl_down_sync(0xffffffffu, w, 1);
                uint32_t w2 = __shfl_down_sync(0xffffffffu, w, 2);
                uint32_t w3 = __shfl_down_sync(0xffffffffu, w, 3);
                if ((lane & 3) == 0) {
                    #pragma unroll
                    for (int r = 0; r < 8; ++r)
                        sta_u4(aPK0 + rdelta[r], mbH0 + rdelta[r], w, w1, w2, w3);
                }
            }
            if (s == 0) {
                float dd0 = xn.x - xc0, dd1 = xn.y - xc1;
                xc0 = xn.x; xc1 = xn.y;
                sDX[(2 * xd2) * 34 + xb]     = dd0;
                sDX[(2 * xd2 + 1) * 34 + xb] = dd1;
                __syncthreads();   // dx visible CTA-wide before epilogue reads
            }
            mbar_wait(mbH0, ph);   // packed h0 complete everywhere

            // ---- L1 via MMA (3-pass hi/lo), pair-redundant 64 rows ----
            float c[4] = {0.0f, 0.0f, 0.0f, 0.0f};
            #pragma unroll
            for (int kk = 0; kk < 8; ++kk) {
                uint32_t ah[4], al[4];
                ldsm4(ah, aW1H + kk * 32);
                ldsm4(al, aW1L + kk * 32);
                const uint32_t* pkk = pkL1 + kk * 576;
                uint32_t w0 = pkk[0],   w1 = pkk[36];
                uint32_t w8 = pkk[288], w9 = pkk[324];
                uint32_t bh0 = prmt(w0, w1, 0x5410u);
                uint32_t bl0 = prmt(w0, w1, 0x7632u);
                uint32_t bh1 = prmt(w8, w9, 0x5410u);
                uint32_t bl1 = prmt(w8, w9, 0x7632u);
                mma16816(c, ah, bh0, bh1);
                mma16816(c, ah, bl0, bl1);
                mma16816(c, al, bh0, bh1);
            }
            // gelu + pack (registers only)
            uint32_t p0 = pack_hilo(gelu_f(c[0] + b1a));
            uint32_t p1 = pack_hilo(gelu_f(c[1] + b1a));
            uint32_t p2 = pack_hilo(gelu_f(c[2] + b1b));
            uint32_t p3 = pack_hilo(gelu_f(c[3] + b1b));
            __syncthreads();       // all local h0 reads done before h1 overwrite
            {
                ull v01, v23;
                asm("mov.b64 %0, {%1, %2};" : "=l"(v01) : "r"(p0), "r"(p1));
                asm("mov.b64 %0, {%1, %2};" : "=l"(v23) : "r"(p2), "r"(p3));
                *h1loc0 = v01;
                *h1loc1 = v23;
                sta_u2(aP2a + pdelta, mbH1 + pdelta, p0, p1);
                sta_u2(aP2b + pdelta, mbH1 + pdelta, p2, p3);
            }
            __syncthreads();       // own-half STS visible to all local warps
            mbar_wait(mbH1, ph);   // peer half arrived

            // ---- W2 GEMM via mma.sync, 3-pass bf16 hi/lo ----
            float acc[4][4];
            #pragma unroll
            for (int nt = 0; nt < 4; ++nt)
                #pragma unroll
                for (int i = 0; i < 4; ++i) acc[nt][i] = 0.0f;

            // own-half k rows (stored in PK, stride 36)
            #pragma unroll
            for (int k2 = 0; k2 < 4; ++k2) {
                uint32_t ah[4], al[4];
                ldsm4(ah, aAH + (half_ * 4 + k2) * 32);
                ldsm4(al, aAL + (half_ * 4 + k2) * 32);
                const uint32_t* pkk = pkOwn + k2 * 576;
                #pragma unroll
                for (int nt = 0; nt < 4; ++nt) {
                    uint32_t w0 = pkk[nt * 8],       w1 = pkk[nt * 8 + 36];
                    uint32_t w8 = pkk[nt * 8 + 288], w9 = pkk[nt * 8 + 324];
                    uint32_t bh0 = prmt(w0, w1, 0x5410u);
                    uint32_t bl0 = prmt(w0, w1, 0x7632u);
                    uint32_t bh1 = prmt(w8, w9, 0x5410u);
                    uint32_t bl1 = prmt(w8, w9, 0x7632u);
                    mma16816(acc[nt], ah, bh0, bh1);
                    mma16816(acc[nt], ah, bl0, bl1);
                    mma16816(acc[nt], al, bh0, bh1);
                }
            }
            // peer-half k rows (stored in PK2, stride 34)
            #pragma unroll
            for (int k2 = 0; k2 < 4; ++k2) {
                uint32_t ah[4], al[4];
                ldsm4(ah, aAH + (kkPeerBase + k2) * 32);
                ldsm4(al, aAL + (kkPeerBase + k2) * 32);
                const uint32_t* pkk = pkPeer + k2 * 544;
                #pragma unroll
                for (int nt = 0; nt < 4; ++nt) {
                    uint32_t w0 = pkk[nt * 8],       w1 = pkk[nt * 8 + 34];
                    uint32_t w8 = pkk[nt * 8 + 272], w9 = pkk[nt * 8 + 306];
                    uint32_t bh0 = prmt(w0, w1, 0x5410u);
                    uint32_t bl0 = prmt(w0, w1, 0x7632u);
                    uint32_t bh1 = prmt(w8, w9, 0x5410u);
                    uint32_t bl1 = prmt(w8, w9, 0x7632u);
                    mma16816(acc[nt], ah, bh0, bh1);
                    mma16816(acc[nt], ah, bl0, bl1);
                    mma16816(acc[nt], al, bh0, bh1);
                }
            }

            // ---- epilogue: tanh(+bias) * dx, reduce over d ----
            {
                float p[8];
                #pragma unroll
                for (int nt = 0; nt < 4; ++nt) {
                    int b0i = nt * 8 + tg * 2;
                    float u00 = tanh_f(acc[nt][0] + b2a);
                    float u01 = tanh_f(acc[nt][1] + b2a);
                    float u10 = tanh_f(acc[nt][2] + b2b);
                    float u11 = tanh_f(acc[nt][3] + b2b);
                    float2 dxa = *reinterpret_cast<const float2*>(&sDX[d0 * 34 + b0i]);
                    float2 dxb = *reinterpret_cast<const float2*>(&sDX[(d0 + 8) * 34 + b0i]);
                    p[nt * 2 + 0] = fmaf(u00, dxa.x, u10 * dxb.x);
                    p[nt * 2 + 1] = fmaf(u01, dxa.y, u11 * dxb.y);
                }
                #pragma unroll
                for (int m = 4; m <= 16; m <<= 1)
                    #pragma unroll
                    for (int i = 0; i < 8; ++i)
                        p[i] += __shfl_xor_sync(0xffffffffu, p[i], m);
                if (lane < 4) {
                    #pragma unroll
                    for (int nt = 0; nt < 4; ++nt) {
                        float2 v = make_float2(p[nt * 2], p[nt * 2 + 1]);
                        *reinterpret_cast<float2*>(&sKP[wid * 32 + nt * 8 + tg * 2]) = v;
                    }
                }
            }
            __syncthreads();
            if (wid < 8) {
                float v = sKP[(2 * wid) * 32 + lane] + sKP[(2 * wid + 1) * 32 + lane];
                float v1 = __shfl_down_sync(0xffffffffu, v, 1);
                float v2 = __shfl_down_sync(0xffffffffu, v, 2);
                float v3 = __shfl_down_sync(0xffffffffu, v, 3);
                if ((lane & 3) == 0) {
                    #pragma unroll
                    for (int r = 0; r < 8; ++r)
                        sta_f4(aKC + rdelta[r], mbK + rdelta[r], v, v1, v2, v3);
                }
            }
            mbar_wait(mbK, ph);    // k complete everywhere

            // ---- RK4 combine (y in registers; write yin/y to sYI) ----
            {
                float4 k4 = *reinterpret_cast<float4*>(&sKC[tid * 4]);
                if (s == 0) {
                    ks0 = k4.x; ks1 = k4.y; ks2 = k4.z; ks3 = k4.w;
                } else {
                    const float w_s = (s == 3) ? 1.0f : 2.0f;
                    ks0 = fmaf(w_s, k4.x, ks0); ks1 = fmaf(w_s, k4.y, ks1);
                    ks2 = fmaf(w_s, k4.z, ks2); ks3 = fmaf(w_s, k4.w, ks3);
                }
                float4 o;
                if (s < 3) {
                    const float cc = (s == 2) ? 1.0f : 0.5f;
                    o.x = fmaf(cc, k4.x, y0); o.y = fmaf(cc, k4.y, y1);
                    o.z = fmaf(cc, k4.z, y2); o.w = fmaf(cc, k4.w, y3);
                } else {
                    const float sx = 1.0f / 6.0f;
                    y0 = fmaf(sx, ks0, y0); y1 = fmaf(sx, ks1, y1);
                    y2 = fmaf(sx, ks2, y2); y3 = fmaf(sx, ks3, y3);
                    o.x = y0; o.y = y1; o.z = y2; o.w = y3;
                }
                *reinterpret_cast<float4*>(&sYI[tid * 4]) = o;
            }
            __syncthreads();       // sYI visible before next L0 / decoder
            if (tid == 0) {        // arm barriers for the next substep
                mbar_expect(mbH0, TX_H0);
                mbar_expect(mbH1, TX_H1);
                mbar_expect(mbK,  TX_K);
            }
            ph ^= 1;
        }
    }

    // ---- decoder + sigmoid (rank 0 CTA) ----
    if (rank == 0 && tid < 32) {
        float acc = db[0];
        #pragma unroll 8
        for (int r = 0; r < 64; ++r) acc = fmaf(dW[r], sYI[r * 32 + tid], acc);
        out[bbase + tid] = __fdividef(1.0f, 1.0f + __expf(-acc));
    }

    cluster_sync_();  // no CTA exits while peers could still address its smem
}

extern "C" void kernel_launch(void* const* d_in, const int* in_sizes, int n_in,
                              void* d_out, int out_size) {
    (void)in_sizes; (void)n_in; (void)out_size;
    const float* xs  = (const float*)d_in[1];
    const float* eW0 = (const float*)d_in[2];
    const float* eb0 = (const float*)d_in[3];
    const float* eW1 = (const float*)d_in[4];
    const float* eb1 = (const float*)d_in[5];
    const float* eW2 = (const float*)d_in[6];
    const float* eb2 = (const float*)d_in[7];
    const float* vW0 = (const float*)d_in[8];
    const float* vb0 = (const float*)d_in[9];
    const float* vW1 = (const float*)d_in[10];
    const float* vb1 = (const float*)d_in[11];
    const float* vW2 = (const float*)d_in[12];
    const float* vb2 = (const float*)d_in[13];
    const float* dW  = (const float*)d_in[14];
    const float* db  = (const float*)d_in[15];
    float* out = (float*)d_out;

    cudaFuncSetAttribute(ncde_kernel, cudaFuncAttributeMaxDynamicSharedMemorySize, SMEM_BYTES);

    cudaLaunchConfig_t cfg = {};
    cfg.gridDim  = dim3(128, 1, 1);
    cfg.blockDim = dim3(512, 1, 1);
    cfg.dynamicSmemBytes = SMEM_BYTES;
    cfg.stream = 0;
    cudaLaunchAttribute attrs[1];
    attrs[0].id = cudaLaunchAttributeClusterDimension;
    attrs[0].val.clusterDim.x = 8;
    attrs[0].val.clusterDim.y = 1;
    attrs[0].val.clusterDim.z = 1;
    cfg.attrs = attrs;
    cfg.numAttrs = 1;

    cudaLaunchKernelEx(&cfg, ncde_kernel,
                       xs, eW0, eb0, eW1, eb1, eW2, eb2,
                       vW0, vb0, vW1, vb1, vW2, vb2, dW, db, out);
}

// round 13
// speedup vs baseline: 2.2871x; 1.1602x over previous
#include <cuda_runtime.h>
#include <cuda_bf16.h>
#include <cstdint>
#include <cstddef>

// ---------------------------------------------------------------------------
// Neural CDE classifier, ONE persistent clustered kernel, bf16 mma.sync
// (3-pass hi/lo ~ fp32) for L1 + W2 GEMMs.
// R13: TWO independent warp-groups per CTA (stream A = batch cols 0-15 on
// warps 0-7, stream B = cols 16-31 on warps 8-15), each with private
// mbarriers + named barriers. Group waits overlap with the other group's
// compute -> hides exchange latency/skew. W2 remapped 1 warp = 1 model row
// (all 32 d) so the k-reduction is a pure in-warp butterfly (KP smem gone).
// grid = 128 CTAs = 16 clusters x 8, 512 thr/CTA, 1 CTA/SM.
// ---------------------------------------------------------------------------

typedef unsigned long long ull;

namespace {
constexpr int NSTEPS = 2047;
constexpr int KP2 = 272;        // A-operand row stride in BYTES (136 bf16)

// byte offsets in dynamic smem
constexpr int SB_AH  = 0;       // 69632  W2 hi bf16 [256][136]
constexpr int SB_AL  = 69632;   // 69632  W2 lo
constexpr int SB_W1H = 139264;  // 17408  W1-slice hi bf16 [64][136]
constexpr int SB_W1L = 156672;  // 17408  W1-slice lo
constexpr int SB_PK  = 174080;  // 18432  packed u32 (hi|lo) [128][36]: h0, then h1 own half
constexpr int SB_PK2 = 192512;  // 8704   peer h1 half, packed u32 [64][34]
constexpr int SB_W0  = 201216;  // 4096   fp32 W0 slice [16][64]
constexpr int SB_YIN = 205312;  // 8192   yin/y [64][32] fp32
constexpr int SB_KC  = 213504;  // 8192   k [64][32] fp32
constexpr int SB_DX  = 221696;  // 4352   dx [32][34] fp32
constexpr int SB_MB  = 226048;  // 48     6 mbarriers (h0 a/b, h1 a/b, k a/b)
constexpr int SMEM_BYTES = 226112;

constexpr uint32_t TX_H0 = 8192;   // per-stream bytes/substep at each CTA
constexpr uint32_t TX_H1 = 4096;
constexpr uint32_t TX_K  = 4096;
}

__device__ __forceinline__ uint32_t s2u(const void* p) {
    return (uint32_t)__cvta_generic_to_shared(p);
}
__device__ __forceinline__ uint32_t mapa_u(uint32_t laddr, int rank) {
    uint32_t r;
    asm("mapa.shared::cluster.u32 %0, %1, %2;" : "=r"(r) : "r"(laddr), "r"(rank));
    return r;
}
__device__ __forceinline__ void sta_f4(uint32_t raddr, uint32_t rmbar,
                                       float a, float b, float c, float d) {
    asm volatile(
        "st.async.shared::cluster.mbarrier::complete_tx::bytes.v4.f32 "
        "[%0], {%1,%2,%3,%4}, [%5];"
        :: "r"(raddr), "f"(a), "f"(b), "f"(c), "f"(d), "r"(rmbar) : "memory");
}
__device__ __forceinline__ void sta_u4(uint32_t raddr, uint32_t rmbar,
                                       uint32_t a, uint32_t b, uint32_t c, uint32_t d) {
    asm volatile(
        "st.async.shared::cluster.mbarrier::complete_tx::bytes.v4.b32 "
        "[%0], {%1,%2,%3,%4}, [%5];"
        :: "r"(raddr), "r"(a), "r"(b), "r"(c), "r"(d), "r"(rmbar) : "memory");
}
__device__ __forceinline__ void sta_u2(uint32_t raddr, uint32_t rmbar, uint32_t a, uint32_t b) {
    ull v;
    asm("mov.b64 %0, {%1, %2};" : "=l"(v) : "r"(a), "r"(b));
    asm volatile(
        "st.async.shared::cluster.mbarrier::complete_tx::bytes.b64 [%0], %1, [%2];"
        :: "r"(raddr), "l"(v), "r"(rmbar) : "memory");
}
__device__ __forceinline__ void mbar_init(uint32_t mbar, uint32_t cnt) {
    asm volatile("mbarrier.init.shared.b64 [%0], %1;" :: "r"(mbar), "r"(cnt) : "memory");
}
__device__ __forceinline__ void mbar_expect(uint32_t mbar, uint32_t bytes) {
    asm volatile("mbarrier.arrive.expect_tx.shared.b64 _, [%0], %1;"
                 :: "r"(mbar), "r"(bytes) : "memory");
}
__device__ __forceinline__ void mbar_wait(uint32_t mbar, uint32_t parity) {
    asm volatile(
        "{\n\t.reg .pred P;\n\t"
        "WL_%=:\n\t"
        "mbarrier.try_wait.parity.acquire.cluster.shared::cta.b64 P, [%0], %1, 0x989680;\n\t"
        "@!P bra WL_%=;\n\t}"
        :: "r"(mbar), "r"(parity) : "memory");
}
__device__ __forceinline__ void cluster_sync_() {
    asm volatile("barrier.cluster.arrive.aligned;" ::: "memory");
    asm volatile("barrier.cluster.wait.aligned;" ::: "memory");
}
__device__ __forceinline__ void bar_g(int barid) {
    asm volatile("bar.sync %0, %1;" :: "r"(barid), "r"(256) : "memory");
}
__device__ __forceinline__ uint32_t prmt(uint32_t a, uint32_t b, uint32_t sel) {
    uint32_t d;
    asm("prmt.b32 %0, %1, %2, %3;" : "=r"(d) : "r"(a), "r"(b), "r"(sel));
    return d;
}
__device__ __forceinline__ float tanh_f(float x) {
    float ax = fabsf(x);
    float e  = __expf(-2.0f * ax);
    float r  = __fdividef(1.0f - e, 1.0f + e);
    return copysignf(r, x);
}
__device__ __forceinline__ float gelu_f(float x) {
    float x3 = x * x * x;
    float t  = tanh_f(0.7978845608028654f * fmaf(0.044715f, x3, x));
    return 0.5f * x * (1.0f + t);
}
__device__ __forceinline__ uint32_t pack_hilo(float a) {
    __nv_bfloat16 hb = __float2bfloat16(a);
    float hf = __bfloat162float(hb);
    __nv_bfloat16 lb = __float2bfloat16(a - hf);
    return (uint32_t)reinterpret_cast<unsigned short&>(hb) |
           ((uint32_t)reinterpret_cast<unsigned short&>(lb) << 16);
}
__device__ __forceinline__ void ldsm4(uint32_t (&r)[4], uint32_t addr) {
    asm volatile("ldmatrix.sync.aligned.m8n8.x4.shared.b16 {%0,%1,%2,%3}, [%4];"
                 : "=r"(r[0]), "=r"(r[1]), "=r"(r[2]), "=r"(r[3]) : "r"(addr));
}
__device__ __forceinline__ void mma16816(float (&c)[4], const uint32_t (&a)[4],
                                         uint32_t b0, uint32_t b1) {
    asm volatile(
        "mma.sync.aligned.m16n8k16.row.col.f32.bf16.bf16.f32 "
        "{%0,%1,%2,%3}, {%4,%5,%6,%7}, {%8,%9}, {%0,%1,%2,%3};"
        : "+f"(c[0]), "+f"(c[1]), "+f"(c[2]), "+f"(c[3])
        : "r"(a[0]), "r"(a[1]), "r"(a[2]), "r"(a[3]), "r"(b0), "r"(b1));
}

__global__ void __launch_bounds__(512, 1)
ncde_kernel(const float* __restrict__ xs,
            const float* __restrict__ eW0, const float* __restrict__ eb0,
            const float* __restrict__ eW1, const float* __restrict__ eb1,
            const float* __restrict__ eW2, const float* __restrict__ eb2,
            const float* __restrict__ vW0, const float* __restrict__ vb0,
            const float* __restrict__ vW1, const float* __restrict__ vb1,
            const float* __restrict__ vW2, const float* __restrict__ vb2,
            const float* __restrict__ dW,  const float* __restrict__ db,
            float* __restrict__ out)
{
    extern __shared__ char smc[];
    const int tid   = threadIdx.x;
    const int lane  = tid & 31;
    const int wid   = tid >> 5;          // 0..15
    const int gid   = wid >> 3;          // warp-group / stream id (0,1)
    const int wl    = wid & 7;           // warp id within group
    const int cb    = gid * 16;          // batch column base of this stream
    const int barid = 1 + gid;
    const int rank  = blockIdx.x & 7;
    const int half_ = rank & 1;
    const int bbase = (blockIdx.x >> 3) * 32;

    float* sW0 = (float*)(smc + SB_W0);
    float* sYI = (float*)(smc + SB_YIN);
    float* sKC = (float*)(smc + SB_KC);
    float* sDX = (float*)(smc + SB_DX);
    uint32_t* sPKw = (uint32_t*)(smc + SB_PK);
    const uint32_t* sP2w = (const uint32_t*)(smc + SB_PK2);

    const uint32_t smem_u = s2u(smc);
    const uint32_t mbH0 = smem_u + SB_MB +      gid * 8;
    const uint32_t mbH1 = smem_u + SB_MB + 16 + gid * 8;
    const uint32_t mbK  = smem_u + SB_MB + 32 + gid * 8;

    if (tid == 0) {
        #pragma unroll
        for (int i = 0; i < 6; ++i) mbar_init(smem_u + SB_MB + i * 8, 1);
    }

    // per-rank DSMEM address deltas (mapa is affine in the local address)
    uint32_t rdelta[8];
    #pragma unroll
    for (int r = 0; r < 8; ++r) rdelta[r] = mapa_u(smem_u, r) - smem_u;
    const uint32_t pdelta = rdelta[rank ^ 1];

    // xs mapping: thread owns (b = tid>>4, d = 2*(tid&15), +1); warps 0-7 own
    // batches 0-15 (stream A), warps 8-15 own 16-31 (stream B).
    const int xb  = tid >> 4;
    const int xd2 = tid & 15;
    const float* xsrow = xs + (size_t)(bbase + xb) * 2048 * 32 + xd2 * 2;

    float xc0, xc1;
    {
        float2 v = *reinterpret_cast<const float2*>(xsrow);
        xc0 = v.x; xc1 = v.y;
        sKC[(2 * xd2) * 32 + xb]     = v.x;   // stage xs0 d-major for encoder
        sKC[(2 * xd2 + 1) * 32 + xb] = v.y;
    }

    // ---- encoder weights transposed into W2 scratch region (floats) ----
    float* sE0 = (float*)(smc + SB_AH);          // [32][128]
    float* sE1 = sE0 + 4096;                     // [128][128]
    float* sE2 = sE0 + 20480;                    // [128][64]
    float* sEH = sE0 + 28672;                    // [128][32]
    float* sH0e = (float*)(smc + SB_PK);         // [128][32] encoder hidden1
    for (int i = tid; i < 4096;  i += 512) { int r = i & 127, kk = i >> 7; sE0[i] = eW0[r * 32  + kk]; }
    for (int i = tid; i < 16384; i += 512) { int r = i & 127, kk = i >> 7; sE1[i] = eW1[r * 128 + kk]; }
    for (int i = tid; i < 8192;  i += 512) { int r = i & 63,  kk = i >> 6; sE2[i] = eW2[r * 128 + kk]; }
    __syncthreads();

    // ---- encoder (replicated per CTA): sKC(xs0) -> sH0e -> sEH -> sYI ----
    {
        int b = lane, rbase = wid * 8;
        float acc[8];
        #pragma unroll
        for (int j = 0; j < 8; ++j) acc[j] = eb0[rbase + j];
        for (int kk = 0; kk < 32; ++kk) {
            float x = sKC[kk * 32 + b];
            #pragma unroll
            for (int j = 0; j < 8; ++j) acc[j] = fmaf(sE0[kk * 128 + rbase + j], x, acc[j]);
        }
        #pragma unroll
        for (int j = 0; j < 8; ++j) sH0e[(rbase + j) * 32 + b] = fmaxf(acc[j], 0.0f);
    }
    __syncthreads();
    {
        int b = lane, rbase = wid * 8;
        float acc[8];
        #pragma unroll
        for (int j = 0; j < 8; ++j) acc[j] = eb1[rbase + j];
        for (int kk = 0; kk < 128; ++kk) {
            float x = sH0e[kk * 32 + b];
            #pragma unroll
            for (int j = 0; j < 8; ++j) acc[j] = fmaf(sE1[kk * 128 + rbase + j], x, acc[j]);
        }
        #pragma unroll
        for (int j = 0; j < 8; ++j) sEH[(rbase + j) * 32 + b] = fmaxf(acc[j], 0.0f);
    }
    __syncthreads();
    {
        int b = lane, rbase = wid * 4;
        float acc[4];
        #pragma unroll
        for (int j = 0; j < 4; ++j) acc[j] = eb2[rbase + j];
        for (int kk = 0; kk < 128; ++kk) {
            float x = sEH[kk * 32 + b];
            #pragma unroll
            for (int j = 0; j < 4; ++j) acc[j] = fmaf(sE2[kk * 64 + rbase + j], x, acc[j]);
        }
        #pragma unroll
        for (int j = 0; j < 4; ++j) sYI[(rbase + j) * 32 + b] = acc[j];
    }
    __syncthreads();

    // ---- build static bf16 hi/lo operands (overwrites encoder scratch) ----
    for (int i = tid; i < 32768; i += 512) {        // W2 slice [256 m][128 k]
        int m = i >> 7, k = i & 127;
        float w = vW2[(size_t)(rank * 256 + m) * 128 + k];
        __nv_bfloat16 hb = __float2bfloat16(w);
        float hf = __bfloat162float(hb);
        __nv_bfloat16 lb = __float2bfloat16(w - hf);
        *(__nv_bfloat16*)(smc + SB_AH + m * KP2 + k * 2) = hb;
        *(__nv_bfloat16*)(smc + SB_AL + m * KP2 + k * 2) = lb;
    }
    for (int i = tid; i < 8192; i += 512) {         // W1 slice [64 m][128 k]
        int m = i >> 7, k = i & 127;
        float w = vW1[(size_t)(half_ * 64 + m) * 128 + k];
        __nv_bfloat16 hb = __float2bfloat16(w);
        float hf = __bfloat162float(hb);
        __nv_bfloat16 lb = __float2bfloat16(w - hf);
        *(__nv_bfloat16*)(smc + SB_W1H + m * KP2 + k * 2) = hb;
        *(__nv_bfloat16*)(smc + SB_W1L + m * KP2 + k * 2) = lb;
    }
    for (int i = tid; i < 1024; i += 512) {         // W0 slice fp32 [16][64]
        int kk = i & 63, r = i >> 6;
        sW0[i] = vW0[(rank * 16 + r) * 64 + kk];
    }

    __syncthreads();
    if (tid == 0) {
        mbar_expect(smem_u + SB_MB + 0,  TX_H0);
        mbar_expect(smem_u + SB_MB + 8,  TX_H0);
        mbar_expect(smem_u + SB_MB + 16, TX_H1);
        mbar_expect(smem_u + SB_MB + 24, TX_H1);
        mbar_expect(smem_u + SB_MB + 32, TX_K);
        mbar_expect(smem_u + SB_MB + 40, TX_K);
    }
    cluster_sync_();

    // ---- per-thread invariants ----
    const int g  = lane >> 2;
    const int tg = lane & 3;

    // L0: warp wl computes h0 rows 2wl (lanes 0-15) / 2wl+1 (lanes 16-31),
    // cols cb + (lane&15)
    const int row2 = 2 * wl + (lane >> 4);
    const int cL0  = lane & 15;
    const float b0s = vb0[rank * 16 + row2];
    const float* wrow0 = sW0 + row2 * 64;
    const uint32_t aPK0 = smem_u + SB_PK + (uint32_t)((rank * 16 + row2) * 36 + cb + cL0) * 4;

    // L1-MMA: mtile = wl>>1 (16 W1 rows), ntile = wl&1 (8 cols)
    const int mtile = wl >> 1;
    const int ntile = wl & 1;
    const float b1a = vb1[half_ * 64 + mtile * 16 + g];
    const float b1b = vb1[half_ * 64 + mtile * 16 + g + 8];
    const uint32_t aW1H = smem_u + SB_W1H + (uint32_t)(mtile * 16 + (lane & 15)) * KP2 + (lane >> 4) * 16;
    const uint32_t aW1L = aW1H + (SB_W1L - SB_W1H);
    const uint32_t* pkL1 = sPKw + tg * 72 + cb + ntile * 8 + g;

    // h1 outputs
    const int m0r = mtile * 16 + g;
    const int c1  = cb + ntile * 8 + tg * 2;
    ull* h1loc0 = (ull*)(sPKw + (half_ * 64 + m0r) * 36 + c1);
    ull* h1loc1 = (ull*)(sPKw + (half_ * 64 + m0r + 8) * 36 + c1);
    const uint32_t aP2a = smem_u + SB_PK2 + (uint32_t)(m0r * 34 + c1) * 4;
    const uint32_t aP2b = aP2a + 8 * 34 * 4;

    // W2-MMA: warp wl = model row rank*8+wl; A local rows wl*32 + mt*16 ..
    uint32_t aA[2], aAl[2];
    #pragma unroll
    for (int mt = 0; mt < 2; ++mt) {
        aA[mt] = smem_u + SB_AH + (uint32_t)(wl * 32 + mt * 16 + (lane & 15)) * KP2 + (lane >> 4) * 16;
        aAl[mt] = aA[mt] + (SB_AL - SB_AH);
    }
    const uint32_t* pkOwn  = sPKw + half_ * 2304 + tg * 72 + cb + g;
    const uint32_t* pkPeer = sP2w + tg * 68 + cb + g;
    const int ksOwn  = half_ * 4;
    const int ksPeer = (1 - half_) * 4;

    // epilogue invariants
    float b2r[2][2];
    #pragma unroll
    for (int mt = 0; mt < 2; ++mt) {
        b2r[mt][0] = vb2[rank * 256 + wl * 32 + mt * 16 + g];
        b2r[mt][1] = vb2[rank * 256 + wl * 32 + mt * 16 + g + 8];
    }
    const float* dxb = sDX + g * 34 + cb + tg * 2;
    const uint32_t aKC = smem_u + SB_KC + (uint32_t)((rank * 8 + wl) * 32 + cb) * 4 + (lane >> 1) * 16;

    // RK4 ownership: group thread ti owns y row ti>>2, cols cb + (ti&3)*4 ..+3
    const int ti = wl * 32 + lane;
    const int ybase = (ti >> 2) * 32 + cb + (ti & 3) * 4;
    float y0 = sYI[ybase + 0], y1 = sYI[ybase + 1];
    float y2 = sYI[ybase + 2], y3 = sYI[ybase + 3];

    uint32_t ph = 0;
    float2 xnA = *reinterpret_cast<const float2*>(xsrow + (size_t)1 * 32);
    float2 xnB = *reinterpret_cast<const float2*>(xsrow + (size_t)2 * 32);

    // ---- main RK4 scan ----
    for (int t = 0; t < NSTEPS; ++t) {
        float2 xn = xnA;
        {
            int tn = (t + 3 <= 2047) ? (t + 3) : 2047;
            xnA = xnB;
            xnB = *reinterpret_cast<const float2*>(xsrow + (size_t)tn * 32);
        }
        float ks0, ks1, ks2, ks3;

        #pragma unroll
        for (int s = 0; s < 4; ++s) {
            // ---- L0: h0[row2][cb+cL0] = gelu(W0row . yin + b0), packed push
            {
                float a = b0s;
                #pragma unroll
                for (int k4 = 0; k4 < 16; ++k4) {
                    float4 w4 = *reinterpret_cast<const float4*>(wrow0 + k4 * 4);
                    a = fmaf(w4.x, sYI[(k4 * 4 + 0) * 32 + cb + cL0], a);
                    a = fmaf(w4.y, sYI[(k4 * 4 + 1) * 32 + cb + cL0], a);
                    a = fmaf(w4.z, sYI[(k4 * 4 + 2) * 32 + cb + cL0], a);
                    a = fmaf(w4.w, sYI[(k4 * 4 + 3) * 32 + cb + cL0], a);
                }
                uint32_t w = pack_hilo(gelu_f(a));
                uint32_t w1 = __shfl_down_sync(0xffffffffu, w, 1);
                uint32_t w2 = __shfl_down_sync(0xffffffffu, w, 2);
                uint32_t w3 = __shfl_down_sync(0xffffffffu, w, 3);
                if ((lane & 3) == 0) {
                    #pragma unroll
                    for (int r = 0; r < 8; ++r)
                        sta_u4(aPK0 + rdelta[r], mbH0 + rdelta[r], w, w1, w2, w3);
                }
            }
            if (s == 0) {   // dx for this step (own-stream columns only)
                float dd0 = xn.x - xc0, dd1 = xn.y - xc1;
                xc0 = xn.x; xc1 = xn.y;
                sDX[(2 * xd2) * 34 + xb]     = dd0;
                sDX[(2 * xd2 + 1) * 34 + xb] = dd1;
            }
            mbar_wait(mbH0, ph);   // packed h0 (and peer dx? no: own dx) ready

            // ---- L1 via MMA (3-pass hi/lo) ----
            float c[4] = {0.0f, 0.0f, 0.0f, 0.0f};
            #pragma unroll
            for (int kk = 0; kk < 8; ++kk) {
                uint32_t ah[4], al[4];
                ldsm4(ah, aW1H + kk * 32);
                ldsm4(al, aW1L + kk * 32);
                const uint32_t* pkk = pkL1 + kk * 576;
                uint32_t w0 = pkk[0],   w1 = pkk[36];
                uint32_t w8 = pkk[288], w9 = pkk[324];
                uint32_t bh0 = prmt(w0, w1, 0x5410u);
                uint32_t bl0 = prmt(w0, w1, 0x7632u);
                uint32_t bh1 = prmt(w8, w9, 0x5410u);
                uint32_t bl1 = prmt(w8, w9, 0x7632u);
                mma16816(c, ah, bh0, bh1);
                mma16816(c, ah, bl0, bl1);
                mma16816(c, al, bh0, bh1);
            }
            uint32_t p0 = pack_hilo(gelu_f(c[0] + b1a));
            uint32_t p1 = pack_hilo(gelu_f(c[1] + b1a));
            uint32_t p2 = pack_hilo(gelu_f(c[2] + b1b));
            uint32_t p3 = pack_hilo(gelu_f(c[3] + b1b));
            bar_g(barid);          // group done reading h0 (and dx written)
            {
                ull v01, v23;
                asm("mov.b64 %0, {%1, %2};" : "=l"(v01) : "r"(p0), "r"(p1));
                asm("mov.b64 %0, {%1, %2};" : "=l"(v23) : "r"(p2), "r"(p3));
                *h1loc0 = v01;
                *h1loc1 = v23;
                sta_u2(aP2a + pdelta, mbH1 + pdelta, p0, p1);
                sta_u2(aP2b + pdelta, mbH1 + pdelta, p2, p3);
            }
            bar_g(barid);          // own-half h1 visible to whole group
            mbar_wait(mbH1, ph);   // peer half arrived

            // ---- W2 GEMM: warp = model row, acc[mt][nt][4] ----
            float acc[2][2][4];
            #pragma unroll
            for (int mt = 0; mt < 2; ++mt)
                #pragma unroll
                for (int nt = 0; nt < 2; ++nt)
                    #pragma unroll
                    for (int i = 0; i < 4; ++i) acc[mt][nt][i] = 0.0f;

            #pragma unroll
            for (int k2 = 0; k2 < 4; ++k2) {      // own half k rows
                uint32_t ah0[4], al0[4], ah1[4], al1[4];
                ldsm4(ah0, aA[0]  + (ksOwn + k2) * 32);
                ldsm4(al0, aAl[0] + (ksOwn + k2) * 32);
                ldsm4(ah1, aA[1]  + (ksOwn + k2) * 32);
                ldsm4(al1, aAl[1] + (ksOwn + k2) * 32);
                const uint32_t* pkk = pkOwn + k2 * 576;
                #pragma unroll
                for (int nt = 0; nt < 2; ++nt) {
                    uint32_t w0 = pkk[nt * 8],       w1 = pkk[nt * 8 + 36];
                    uint32_t w8 = pkk[nt * 8 + 288], w9 = pkk[nt * 8 + 324];
                    uint32_t bh0 = prmt(w0, w1, 0x5410u);
                    uint32_t bl0 = prmt(w0, w1, 0x7632u);
                    uint32_t bh1 = prmt(w8, w9, 0x5410u);
                    uint32_t bl1 = prmt(w8, w9, 0x7632u);
                    mma16816(acc[0][nt], ah0, bh0, bh1);
                    mma16816(acc[0][nt], ah0, bl0, bl1);
                    mma16816(acc[0][nt], al0, bh0, bh1);
                    mma16816(acc[1][nt], ah1, bh0, bh1);
                    mma16816(acc[1][nt], ah1, bl0, bl1);
                    mma16816(acc[1][nt], al1, bh0, bh1);
                }
            }
            #pragma unroll
            for (int k2 = 0; k2 < 4; ++k2) {      // peer half k rows
                uint32_t ah0[4], al0[4], ah1[4], al1[4];
                ldsm4(ah0, aA[0]  + (ksPeer + k2) * 32);
                ldsm4(al0, aAl[0] + (ksPeer + k2) * 32);
                ldsm4(ah1, aA[1]  + (ksPeer + k2) * 32);
                ldsm4(al1, aAl[1] + (ksPeer + k2) * 32);
                const uint32_t* pkk = pkPeer + k2 * 544;
                #pragma unroll
                for (int nt = 0; nt < 2; ++nt) {
                    uint32_t w0 = pkk[nt * 8],       w1 = pkk[nt * 8 + 34];
                    uint32_t w8 = pkk[nt * 8 + 272], w9 = pkk[nt * 8 + 306];
                    uint32_t bh0 = prmt(w0, w1, 0x5410u);
                    uint32_t bl0 = prmt(w0, w1, 0x7632u);
                    uint32_t bh1 = prmt(w8, w9, 0x5410u);
                    uint32_t bl1 = prmt(w8, w9, 0x7632u);
                    mma16816(acc[0][nt], ah0, bh0, bh1);
                    mma16816(acc[0][nt], ah0, bl0, bl1);
                    mma16816(acc[0][nt], al0, bh0, bh1);
                    mma16816(acc[1][nt], ah1, bh0, bh1);
                    mma16816(acc[1][nt], ah1, bl0, bl1);
                    mma16816(acc[1][nt], al1, bh0, bh1);
                }
            }

            // ---- epilogue: tanh(+bias)*dx, full d-reduction in-warp ----
            {
                float p[4] = {0.0f, 0.0f, 0.0f, 0.0f};
                #pragma unroll
                for (int mt = 0; mt < 2; ++mt)
                    #pragma unroll
                    for (int rp = 0; rp < 2; ++rp) {
                        const float bias = b2r[mt][rp];
                        const float* dxr = dxb + (mt * 16 + rp * 8) * 34;
                        #pragma unroll
                        for (int nt = 0; nt < 2; ++nt) {
                            float u0 = tanh_f(acc[mt][nt][rp * 2 + 0] + bias);
                            float u1 = tanh_f(acc[mt][nt][rp * 2 + 1] + bias);
                            float2 dx2 = *reinterpret_cast<const float2*>(dxr + nt * 8);
                            p[nt * 2 + 0] = fmaf(u0, dx2.x, p[nt * 2 + 0]);
                            p[nt * 2 + 1] = fmaf(u1, dx2.y, p[nt * 2 + 1]);
                        }
                    }
                #pragma unroll
                for (int m = 4; m <= 16; m <<= 1)
                    #pragma unroll
                    for (int i = 0; i < 4; ++i)
                        p[i] += __shfl_xor_sync(0xffffffffu, p[i], m);
                float s0 = __shfl_down_sync(0xffffffffu, p[0], 1);
                float s1 = __shfl_down_sync(0xffffffffu, p[1], 1);
                float s2 = __shfl_down_sync(0xffffffffu, p[2], 1);
                float s3 = __shfl_down_sync(0xffffffffu, p[3], 1);
                if (lane == 0 || lane == 2) {
                    #pragma unroll
                    for (int r = 0; r < 8; ++r) {
                        sta_f4(aKC + rdelta[r],      mbK + rdelta[r], p[0], p[1], s0, s1);
                        sta_f4(aKC + 32 + rdelta[r], mbK + rdelta[r], p[2], p[3], s2, s3);
                    }
                }
            }
            mbar_wait(mbK, ph);    // stream k complete everywhere
            if (wl == 0 && lane == 0) {   // re-arm this stream's barriers
                mbar_expect(mbH0, TX_H0);
                mbar_expect(mbH1, TX_H1);
                mbar_expect(mbK,  TX_K);
            }

            // ---- RK4 combine (y in registers) ----
            {
                float4 k4 = *reinterpret_cast<const float4*>(&sKC[ybase]);
                if (s == 0) {
                    ks0 = k4.x; ks1 = k4.y; ks2 = k4.z; ks3 = k4.w;
                } else {
                    const float w_s = (s == 3) ? 1.0f : 2.0f;
                    ks0 = fmaf(w_s, k4.x, ks0); ks1 = fmaf(w_s, k4.y, ks1);
                    ks2 = fmaf(w_s, k4.z, ks2); ks3 = fmaf(w_s, k4.w, ks3);
                }
                float4 o;
                if (s < 3) {
                    const float cc = (s == 2) ? 1.0f : 0.5f;
                    o.x = fmaf(cc, k4.x, y0); o.y = fmaf(cc, k4.y, y1);
                    o.z = fmaf(cc, k4.z, y2); o.w = fmaf(cc, k4.w, y3);
                } else {
                    const float sx = 1.0f / 6.0f;
                    y0 = fmaf(sx, ks0, y0); y1 = fmaf(sx, ks1, y1);
                    y2 = fmaf(sx, ks2, y2); y3 = fmaf(sx, ks3, y3);
                    o.x = y0; o.y = y1; o.z = y2; o.w = y3;
                }
                *reinterpret_cast<float4*>(&sYI[ybase]) = o;
            }
            bar_g(barid);          // group yin visible before next L0
            ph ^= 1;
        }
    }

    __syncthreads();               // both streams' final y in sYI

    // ---- decoder + sigmoid (rank 0 CTA) ----
    if (rank == 0 && tid < 32) {
        float acc = db[0];
        #pragma unroll 8
        for (int r = 0; r < 64; ++r) acc = fmaf(dW[r], sYI[r * 32 + tid], acc);
        out[bbase + tid] = __fdividef(1.0f, 1.0f + __expf(-acc));
    }

    cluster_sync_();  // no CTA exits while peers could still address its smem
}

extern "C" void kernel_launch(void* const* d_in, const int* in_sizes, int n_in,
                              void* d_out, int out_size) {
    (void)in_sizes; (void)n_in; (void)out_size;
    const float* xs  = (const float*)d_in[1];
    const float* eW0 = (const float*)d_in[2];
    const float* eb0 = (const float*)d_in[3];
    const float* eW1 = (const float*)d_in[4];
    const float* eb1 = (const float*)d_in[5];
    const float* eW2 = (const float*)d_in[6];
    const float* eb2 = (const float*)d_in[7];
    const float* vW0 = (const float*)d_in[8];
    const float* vb0 = (const float*)d_in[9];
    const float* vW1 = (const float*)d_in[10];
    const float* vb1 = (const float*)d_in[11];
    const float* vW2 = (const float*)d_in[12];
    const float* vb2 = (const float*)d_in[13];
    const float* dW  = (const float*)d_in[14];
    const float* db  = (const float*)d_in[15];
    float* out = (float*)d_out;

    cudaFuncSetAttribute(ncde_kernel, cudaFuncAttributeMaxDynamicSharedMemorySize, SMEM_BYTES);

    cudaLaunchConfig_t cfg = {};
    cfg.gridDim  = dim3(128, 1, 1);
    cfg.blockDim = dim3(512, 1, 1);
    cfg.dynamicSmemBytes = SMEM_BYTES;
    cfg.stream = 0;
    cudaLaunchAttribute attrs[1];
    attrs[0].id = cudaLaunchAttributeClusterDimension;
    attrs[0].val.clusterDim.x = 8;
    attrs[0].val.clusterDim.y = 1;
    attrs[0].val.clusterDim.z = 1;
    cfg.attrs = attrs;
    cfg.numAttrs = 1;

    cudaLaunchKernelEx(&cfg, ncde_kernel,
                       xs, eW0, eb0, eW1, eb1, eW2, eb2,
                       vW0, vb0, vW1, vb1, vW2, vb2, dW, db, out);
}